// round 8
// baseline (speedup 1.0000x reference)
#include <cuda_runtime.h>
#include <cuda_bf16.h>
#include <cstdint>

typedef __nv_bfloat16 bf16;
#define NOUT 4928

// ---------------- scratch (device globals; sizes in elements) ----------------
__device__ __align__(16) bf16 g_Xs5[(size_t)2048 * 6144];     // res5 aug [pos][3*2048]
__device__ __align__(16) bf16 g_W1 [(size_t)512 * 55296];     // conv1 W aug
__device__ __align__(16) bf16 g_X1 [(size_t)2048 * 1536];     // x1 aug (moving 512 ch only)
__device__ __align__(16) bf16 g_W2 [(size_t)1024 * 13824];    // conv2 W aug (512 moving ch)
__device__ __align__(16) bf16 g_X2 [(size_t)2048 * 3072];     // x2 aug
__device__ __align__(16) bf16 g_W3 [(size_t)4992 * 3072];     // cls1 W aug (padded)
__device__ __align__(16) bf16 g_Xr2[(size_t)131072 * 768];    // res2 aug
__device__ __align__(16) bf16 g_W4 [(size_t)64 * 6912];       // c1a W aug
__device__ float g_gp [8 * 512];                              // global pool values
__device__ float g_C9 [(size_t)8 * 1024 * 9];                 // per-class gp correction
__device__ float g_cls1T[(size_t)2048 * NOUT];
__device__ float g_c1aT [(size_t)131072 * 48];

// ---------------- helpers ----------------
__device__ __forceinline__ void split2(float v, bf16& h, bf16& l) {
    h = __float2bfloat16(v);
    l = __float2bfloat16(v - __bfloat162float(h));
}
__device__ __forceinline__ unsigned pkb(bf16 a, bf16 b) {
    return (unsigned)__bfloat16_as_ushort(a) | ((unsigned)__bfloat16_as_ushort(b) << 16);
}
__device__ __forceinline__ unsigned s2u(const void* p) {
    return (unsigned)__cvta_generic_to_shared(p);
}
__device__ __forceinline__ void cpa16(unsigned d, const void* s, unsigned sz) {
    asm volatile("cp.async.ca.shared.global [%0], [%1], 16, %2;" :: "r"(d), "l"(s), "r"(sz));
}
__device__ __forceinline__ void cpa_commit() {
    asm volatile("cp.async.commit_group;" ::: "memory");
}
template<int N> __device__ __forceinline__ void cpa_wait() {
    asm volatile("cp.async.wait_group %0;" :: "n"(N) : "memory");
}
__device__ __forceinline__ void ldm4(unsigned* r, unsigned a) {
    asm volatile("ldmatrix.sync.aligned.m8n8.x4.shared.b16 {%0,%1,%2,%3}, [%4];"
        : "=r"(r[0]), "=r"(r[1]), "=r"(r[2]), "=r"(r[3]) : "r"(a));
}
__device__ __forceinline__ void mma16816(float* d, const unsigned* a, const unsigned* b) {
    asm volatile("mma.sync.aligned.m16n8k16.row.col.f32.bf16.bf16.f32 "
        "{%0,%1,%2,%3}, {%4,%5,%6,%7}, {%8,%9}, {%0,%1,%2,%3};"
        : "+f"(d[0]), "+f"(d[1]), "+f"(d[2]), "+f"(d[3])
        : "r"(a[0]), "r"(a[1]), "r"(a[2]), "r"(a[3]), "r"(b[0]), "r"(b[1]));
}

// =====================================================================
// HMMA GEMM, 8 warps as (8/WS)m x WS n, BK=32, 3-stage cp.async pipeline.
// SMEM rows 80B stride => conflict-free ldmatrix.
// epi: 0 = BN+ReLU -> aug bf16; 1 = +bias -> fp32; 2 = BN+ReLU -> fp32;
//      3 = +C9corr, BN+ReLU -> aug bf16 (conv2, 16x16 image assumed)
// =====================================================================
template<int BM, int BN, int WS, bool CONV3>
__global__ __launch_bounds__(256) void gemm_mma(
    const bf16* __restrict__ A, const bf16* __restrict__ B,
    int C3, int imh, int imw, int nk, int Kb,
    int epi, int nvalid,
    const float* __restrict__ scale, const float* __restrict__ shift,
    const float* __restrict__ bias, const float* __restrict__ corr,
    bf16* __restrict__ Oaug, int outc,
    float* __restrict__ Of, int ofc)
{
    constexpr int WM = BM / (8 / WS), WN = BN / WS;
    constexpr int MT = WM / 16;
    constexpr int NT = WN / 8;
    constexpr int NF = WN / 16;
    constexpr int AJ = BM / 64;
    constexpr int BJ = (BN + 63) / 64;
    constexpr int ABYTES = BM * 80, STG = (BM + BN) * 80;

    extern __shared__ __align__(16) char sm[];
    const int tid = threadIdx.x;
    const int nb = blockIdx.x, mtile = blockIdx.y;
    const int warp = tid >> 5, lane = tid & 31;
    const int m0 = (warp / WS) * WM, n0 = (warp % WS) * WN;
    const unsigned sbase = s2u(sm);
    const int imgpix = imh * imw;
    const int vec = tid & 3;

    int arow[AJ], ay[AJ], ax[AJ], apb[AJ];
#pragma unroll
    for (int j = 0; j < AJ; j++) {
        arow[j] = (tid >> 2) + j * 64;
        int g = mtile * BM + arow[j];
        if (CONV3) {
            int bb = g / imgpix, lp = g - bb * imgpix;
            ay[j] = lp / imw; ax[j] = lp - ay[j] * imw; apb[j] = bb * imgpix;
        } else { ay[j] = 0; ax[j] = 0; apb[j] = g; }
    }

    auto load_chunk = [&](int kc, int st) {
        unsigned Ab = sbase + st * STG;
        unsigned Bb = Ab + ABYTES;
        int k0 = kc * 32;
        int dy = 0, dx = 0, cb = k0;
        if (CONV3) {
            int rk = k0 / C3; cb = k0 - rk * C3;
            int r3 = rk / 3; dy = r3 - 1; dx = rk - r3 * 3 - 1;
        }
#pragma unroll
        for (int j = 0; j < AJ; j++) {
            const bf16* src;
            unsigned sz = 16;
            if (CONV3) {
                int y2 = ay[j] + dy, x2 = ax[j] + dx;
                bool v = ((unsigned)y2 < (unsigned)imh) && ((unsigned)x2 < (unsigned)imw);
                src = A + (size_t)(apb[j] + y2 * imw + x2) * C3 + cb + vec * 8;
                if (!v) { src = A; sz = 0; }
            } else {
                src = A + (size_t)apb[j] * C3 + k0 + vec * 8;
            }
            cpa16(Ab + arow[j] * 80 + vec * 16, src, sz);
        }
#pragma unroll
        for (int j = 0; j < BJ; j++) {
            int row = (tid >> 2) + j * 64;
            if ((BN % 64 == 0) || row < BN)
                cpa16(Bb + row * 80 + vec * 16,
                      B + (size_t)(nb * BN + row) * Kb + k0 + vec * 8, 16);
        }
    };

    float acc[MT][NT][4];
#pragma unroll
    for (int a = 0; a < MT; a++)
#pragma unroll
        for (int b2 = 0; b2 < NT; b2++)
#pragma unroll
            for (int c = 0; c < 4; c++) acc[a][b2][c] = 0.f;

    auto compute = [&](int st) {
        unsigned Ab = sbase + st * STG;
        unsigned Bb = Ab + ABYTES;
#pragma unroll
        for (int step = 0; step < 2; step++) {
            unsigned af[MT][4], bfr[NF][4];
            {
                int ch = step * 2 + (lane >> 4);
#pragma unroll
                for (int i = 0; i < MT; i++)
                    ldm4(af[i], Ab + (m0 + 16 * i + (lane & 15)) * 80 + ch * 16);
            }
            {
                int rr = (lane & 7) + ((lane >> 4) << 3);
                int ch = step * 2 + ((lane >> 3) & 1);
#pragma unroll
                for (int i = 0; i < NF; i++)
                    ldm4(bfr[i], Bb + (n0 + 16 * i + rr) * 80 + ch * 16);
            }
#pragma unroll
            for (int mt = 0; mt < MT; mt++)
#pragma unroll
                for (int nt = 0; nt < NT; nt++)
                    mma16816(acc[mt][nt], af[mt], &bfr[nt >> 1][(nt & 1) * 2]);
        }
    };

    load_chunk(0, 0);
    cpa_commit();
    if (nk > 1) load_chunk(1, 1);
    cpa_commit();
    int st2 = 2;
    for (int kc = 0; kc < nk; kc++) {
        cpa_wait<1>();
        __syncthreads();
        if (kc + 2 < nk) {
            load_chunk(kc + 2, st2);
            if (++st2 == 3) st2 = 0;
        }
        cpa_commit();
        compute(kc % 3);
    }

    // ---- epilogue ----
#pragma unroll
    for (int mt = 0; mt < MT; mt++)
#pragma unroll
        for (int nt = 0; nt < NT; nt++) {
            float* d = acc[mt][nt];
            int row = mtile * BM + m0 + mt * 16 + (lane >> 2);
            int col = nb * BN + n0 + nt * 8 + (lane & 3) * 2;
#pragma unroll
            for (int h = 0; h < 2; h++) {
                int r = row + h * 8;
                float v0 = d[h * 2 + 0], v1 = d[h * 2 + 1];
                if (epi == 0 || epi == 3) {
                    if (epi == 3) {
                        int bb = r >> 8, lp = r & 255;
                        int y = lp >> 4, xp = lp & 15;
                        int cls = ((y == 0) ? 0 : ((y == 15) ? 6 : 3))
                                + ((xp == 0) ? 0 : ((xp == 15) ? 2 : 1));
                        const float* cp = corr + (size_t)bb * 1024 * 9;
                        v0 += cp[(size_t)col * 9 + cls];
                        v1 += cp[(size_t)(col + 1) * 9 + cls];
                    }
                    v0 = fmaxf(fmaf(v0, scale[col], shift[col]), 0.f);
                    v1 = fmaxf(fmaf(v1, scale[col + 1], shift[col + 1]), 0.f);
                    bf16 h0, l0, h1, l1; split2(v0, h0, l0); split2(v1, h1, l1);
                    size_t base = (size_t)r * 3 * outc + col;
                    *(unsigned*)(Oaug + base) = pkb(h0, h1);
                    *(unsigned*)(Oaug + base + outc) = pkb(l0, l1);
                    *(unsigned*)(Oaug + base + 2 * outc) = pkb(h0, h1);
                } else if (epi == 1) {
                    if (col < nvalid) {
                        float2 o = make_float2(v0 + bias[col], v1 + bias[col + 1]);
                        *(float2*)(Of + (size_t)r * ofc + col) = o;
                    }
                } else {
                    if (col < nvalid) {
                        float2 o;
                        o.x = fmaxf(fmaf(v0, scale[col], shift[col]), 0.f);
                        o.y = fmaxf(fmaf(v1, scale[col + 1], shift[col + 1]), 0.f);
                        *(float2*)(Of + (size_t)r * ofc + col) = o;
                    }
                }
            }
        }
}

// ---------------- prep: NCHW fp32 -> [pos][3C] augmented bf16 ----------------
__global__ __launch_bounds__(256) void split_aug(
    const float* __restrict__ in, bf16* __restrict__ out, int C, int HW)
{
    __shared__ float t[32][33];
    const int b = blockIdx.z, c0 = blockIdx.y * 32, p0 = blockIdx.x * 32;
    const int tx = threadIdx.x & 31, ty = threadIdx.x >> 5;
#pragma unroll
    for (int r = 0; r < 4; r++)
        t[ty + 8 * r][tx] = in[((size_t)b * C + c0 + ty + 8 * r) * HW + p0 + tx];
    __syncthreads();
#pragma unroll
    for (int r = 0; r < 4; r++) {
        int p = p0 + ty + 8 * r;
        float v = t[tx][ty + 8 * r];
        bf16 h, l; split2(v, h, l);
        size_t o = ((size_t)b * HW + p) * 3 * C + c0 + tx;
        out[o] = h; out[o + C] = l; out[o + 2 * C] = h;
    }
}

// ---------------- prep: conv1 weight OIHW -> [oc][tap][3C] augmented ----------------
__global__ __launch_bounds__(256) void wsplit_conv_aug(
    const float* __restrict__ w, bf16* __restrict__ out, int C, int OC)
{
    int idx = blockIdx.x * 256 + threadIdx.x;
    int oc = idx / (9 * C); int rem = idx - oc * 9 * C;
    int tap = rem / C; int c = rem - tap * C;
    float v = (oc < OC) ? w[((size_t)oc * C + c) * 9 + tap] : 0.f;
    bf16 h, l; split2(v, h, l);
    size_t base = (size_t)oc * (27 * C) + (size_t)tap * 3 * C;
    out[base + c] = h; out[base + C + c] = h; out[base + 2 * C + c] = l;
}

// ---------------- prep: conv2 weight, only moving cin 0..511 ----------------
__global__ __launch_bounds__(256) void wsplit_conv2(
    const float* __restrict__ w, bf16* __restrict__ out)
{
    int idx = blockIdx.x * 256 + threadIdx.x;   // 1024 * 9 * 512
    int oc = idx / (9 * 512); int rem = idx - oc * 9 * 512;
    int tap = rem / 512; int c = rem - tap * 512;
    float v = w[((size_t)oc * 1024 + c) * 9 + tap];
    bf16 h, l; split2(v, h, l);
    size_t base = (size_t)oc * 13824 + (size_t)tap * 1536;
    out[base + c] = h; out[base + 512 + c] = h; out[base + 1024 + c] = l;
}

// ---------------- merged small prep: c1a W aug + cls1 W aug ----------------
__global__ __launch_bounds__(256) void wsplit_small(
    const float* __restrict__ aw, const float* __restrict__ c1w,
    bf16* __restrict__ W4, bf16* __restrict__ W3)
{
    const int N4 = 64 * 9 * 256;
    int idx = blockIdx.x * 256 + threadIdx.x;
    if (idx < N4) {
        int oc = idx / (9 * 256); int rem = idx - oc * 9 * 256;
        int tap = rem / 256; int c = rem - tap * 256;
        float v = (oc < 48) ? aw[((size_t)oc * 256 + c) * 9 + tap] : 0.f;
        bf16 h, l; split2(v, h, l);
        size_t base = (size_t)oc * (27 * 256) + (size_t)tap * 768;
        W4[base + c] = h; W4[base + 256 + c] = h; W4[base + 512 + c] = l;
    } else {
        int i2 = idx - N4;
        if (i2 < 4992 * 1024) {
            int oc = i2 >> 10, c = i2 & 1023;
            float v = (oc < NOUT) ? c1w[(size_t)oc * 1024 + c] : 0.f;
            bf16 h, l; split2(v, h, l);
            size_t base = (size_t)oc * 3072;
            W3[base + c] = h; W3[base + 1024 + c] = h; W3[base + 2048 + c] = l;
        }
    }
}

// ---------------- gp reduce: mean over 256 pos of X1 (h+l), deterministic ----------------
__global__ __launch_bounds__(512) void gp_reduce(
    const bf16* __restrict__ X1, float* __restrict__ gp)
{
    const int b = blockIdx.x, c = threadIdx.x;    // c in [0,512)
    float s = 0.f;
    for (int p = 0; p < 256; p++) {
        size_t i = ((size_t)(b * 256 + p)) * 1536 + c;
        s += __bfloat162float(X1[i]) + __bfloat162float(X1[i + 512]);
    }
    gp[b * 512 + c] = s * (1.f / 256.f);
}

// ---------------- C9: per-(b, oc, boundary-class) gp correction ----------------
__global__ __launch_bounds__(128) void c9_kernel(
    const float* __restrict__ w, const float* __restrict__ gp, float* __restrict__ C9)
{
    __shared__ float sgp[512];
    __shared__ float sT[16][9];
    const int b = blockIdx.y, oc0 = blockIdx.x * 16, tid = threadIdx.x;
    for (int i = tid; i < 512; i += 128) sgp[i] = gp[b * 512 + i];
    __syncthreads();

    const int oc = oc0 + (tid >> 3), ln = tid & 7;
    float t[9];
#pragma unroll
    for (int k = 0; k < 9; k++) t[k] = 0.f;
    for (int c = ln * 64; c < ln * 64 + 64; c++) {
        float g = sgp[c];
        const float* wp = w + ((size_t)oc * 1024 + 512 + c) * 9;
#pragma unroll
        for (int k = 0; k < 9; k++) t[k] = fmaf(wp[k], g, t[k]);
    }
#pragma unroll
    for (int o = 4; o; o >>= 1)
#pragma unroll
        for (int k = 0; k < 9; k++) t[k] += __shfl_down_sync(0xffffffffu, t[k], o, 8);
    if (ln == 0)
#pragma unroll
        for (int k = 0; k < 9; k++) sT[tid >> 3][k] = t[k];
    __syncthreads();

    for (int i = tid; i < 144; i += 128) {
        int o = i / 9, cls = i - (i / 9) * 9;
        int fy = cls / 3, fx = cls - fy * 3;
        float s = 0.f;
#pragma unroll
        for (int ky = 0; ky < 3; ky++) {
            if ((fy == 0 && ky == 0) || (fy == 2 && ky == 2)) continue;
#pragma unroll
            for (int kx = 0; kx < 3; kx++) {
                if ((fx == 0 && kx == 0) || (fx == 2 && kx == 2)) continue;
                s += sT[o][ky * 3 + kx];
            }
        }
        C9[((size_t)b * 1024 + oc0 + o) * 9 + cls] = s;
    }
}

// ---------------- fused: c1b + coord + cat-BN + 3-layer dynamic MLP ----------------
__global__ __launch_bounds__(256) void fused_final(
    const float* __restrict__ cls1T, const float* __restrict__ c1aT,
    const float* __restrict__ c1b_w, const float* __restrict__ c1b_b,
    const float* __restrict__ cat_scale, const float* __restrict__ cat_shift,
    float* __restrict__ out)
{
    const int b = blockIdx.y, lpos = blockIdx.x;
    const int ly = lpos >> 4, lx = lpos & 15;
    const int tid = threadIdx.x;
    const int px = tid & 63, q = tid >> 6;
    const int py = px >> 3, pxx = px & 7;

    __shared__ float sP[NOUT];
    __shared__ float sA[48 * 64];
    __shared__ float sI[18 * 64];
    __shared__ float sH0[16 * 64];
    __shared__ float sH1[16 * 64];
    __shared__ float sWb[768 + 16];

    const float* pp = cls1T + (size_t)(b * 256 + lpos) * NOUT;
    for (int i = tid; i < NOUT; i += 256) sP[i] = pp[i];
    for (int i = tid; i < 48 * 64; i += 256) {
        int p = i / 48, ch = i - p * 48;
        int yy = ly * 8 + (p >> 3), xx = lx * 8 + (p & 7);
        sA[ch * 64 + p] = c1aT[((size_t)b * 16384 + yy * 128 + xx) * 48 + ch];
    }
    for (int i = tid; i < 768; i += 256) sWb[i] = c1b_w[i];
    if (tid < 16) sWb[768 + tid] = c1b_b[tid];
    __syncthreads();

#pragma unroll
    for (int jj = 0; jj < 4; jj++) {
        int j = q * 4 + jj;
        float s = sWb[768 + j];
#pragma unroll
        for (int c = 0; c < 48; c++)
            s = fmaf(sA[c * 64 + px], sWb[j * 48 + c], s);
        sI[(2 + j) * 64 + px] = fmaf(s, cat_scale[2 + j], cat_shift[2 + j]);
    }
    if (q == 0) {
        sI[px]      = fmaf((float)pxx * 0.125f, cat_scale[0], cat_shift[0]);
        sI[64 + px] = fmaf((float)py  * 0.125f, cat_scale[1], cat_shift[1]);
    }
    __syncthreads();

#pragma unroll
    for (int jj = 0; jj < 4; jj++) {
        int o = q * 4 + jj;
        float s = sP[288 + o];
#pragma unroll
        for (int c = 0; c < 18; c++)
            s = fmaf(sP[o * 18 + c], sI[c * 64 + px], s);
        sH0[o * 64 + px] = fmaxf(s, 0.f);
    }
    __syncthreads();

#pragma unroll
    for (int jj = 0; jj < 4; jj++) {
        int o = q * 4 + jj;
        float s = sP[560 + o];
#pragma unroll
        for (int c = 0; c < 16; c++)
            s = fmaf(sP[304 + o * 16 + c], sH0[c * 64 + px], s);
        sH1[o * 64 + px] = fmaxf(s, 0.f);
    }
    __syncthreads();

    float hr[16];
#pragma unroll
    for (int c = 0; c < 16; c++) hr[c] = sH1[c * 64 + px];
    const int y = ly * 8 + py, x = lx * 8 + pxx;
    float* ob = out + (((size_t)b * 256) << 14) + (y << 7) + x;
#pragma unroll 4
    for (int oo = 0; oo < 64; oo++) {
        int o = q * 64 + oo;
        float s = sP[4672 + o];
#pragma unroll
        for (int c = 0; c < 16; c++)
            s = fmaf(sP[576 + o * 16 + c], hr[c], s);
        ob[(size_t)o << 14] = s;
    }
}

// ---------------- host launcher ----------------
extern "C" void kernel_launch(void* const* d_in, const int* in_sizes, int n_in,
                              void* d_out, int out_size)
{
    const float* res5 = (const float*)d_in[0];
    const float* res2 = (const float*)d_in[1];
    const float* bw   = (const float*)d_in[2];
    const float* bn1s = (const float*)d_in[3];
    const float* bn1h = (const float*)d_in[4];
    const float* c0w  = (const float*)d_in[5];
    const float* bn2s = (const float*)d_in[6];
    const float* bn2h = (const float*)d_in[7];
    const float* c1w  = (const float*)d_in[8];
    const float* c1b  = (const float*)d_in[9];
    const float* aw   = (const float*)d_in[10];
    const float* bn3s = (const float*)d_in[11];
    const float* bn3h = (const float*)d_in[12];
    const float* bw2  = (const float*)d_in[13];
    const float* bb2  = (const float*)d_in[14];
    const float* cats = (const float*)d_in[15];
    const float* cath = (const float*)d_in[16];
    float* out = (float*)d_out;

    bf16 *Xs5, *W1, *X1, *W2, *X2, *W3, *Xr2, *W4;
    float *gp, *C9, *cls1T, *c1aT;
    cudaGetSymbolAddress((void**)&Xs5, g_Xs5);
    cudaGetSymbolAddress((void**)&W1,  g_W1);
    cudaGetSymbolAddress((void**)&X1,  g_X1);
    cudaGetSymbolAddress((void**)&W2,  g_W2);
    cudaGetSymbolAddress((void**)&X2,  g_X2);
    cudaGetSymbolAddress((void**)&W3,  g_W3);
    cudaGetSymbolAddress((void**)&Xr2, g_Xr2);
    cudaGetSymbolAddress((void**)&W4,  g_W4);
    cudaGetSymbolAddress((void**)&gp,  g_gp);
    cudaGetSymbolAddress((void**)&C9,  g_C9);
    cudaGetSymbolAddress((void**)&cls1T, g_cls1T);
    cudaGetSymbolAddress((void**)&c1aT,  g_c1aT);

    const int SM_C1 = (128 + 64) * 80 * 3;    // 46080
    const int SM_BB = (128 + 128) * 80 * 3;   // 61440
    const int SM_C4 = (256 + 48) * 80 * 3;    // 72960
    cudaFuncSetAttribute(gemm_mma<128, 64, 2, true>,   cudaFuncAttributeMaxDynamicSharedMemorySize, SM_C1);
    cudaFuncSetAttribute(gemm_mma<128, 128, 2, true>,  cudaFuncAttributeMaxDynamicSharedMemorySize, SM_BB);
    cudaFuncSetAttribute(gemm_mma<128, 128, 2, false>, cudaFuncAttributeMaxDynamicSharedMemorySize, SM_BB);
    cudaFuncSetAttribute(gemm_mma<256, 48, 1, true>,   cudaFuncAttributeMaxDynamicSharedMemorySize, SM_C4);

    // ---- prep ----
    split_aug<<<dim3(8, 64, 8), 256>>>(res5, Xs5, 2048, 256);
    split_aug<<<dim3(512, 8, 8), 256>>>(res2, Xr2, 256, 16384);
    wsplit_conv_aug<<<(512 * 9 * 2048) / 256, 256>>>(bw, W1, 2048, 512);
    wsplit_conv2<<<(1024 * 9 * 512) / 256, 256>>>(c0w, W2);
    wsplit_small<<<(64 * 9 * 256 + 4992 * 1024 + 255) / 256, 256>>>(aw, c1w, W4, W3);

    // ---- conv1: [2048 x 55296] * [512 x 55296] -> X1 aug (512 ch) ----
    gemm_mma<128, 64, 2, true><<<dim3(8, 16), 256, SM_C1>>>(
        Xs5, W1, 6144, 16, 16, 1728, 55296, 0, 512,
        bn1s, bn1h, nullptr, nullptr, X1, 512, nullptr, 0);
    // ---- gp + C9 correction ----
    gp_reduce<<<8, 512>>>(X1, gp);
    c9_kernel<<<dim3(64, 8), 128>>>(c0w, gp, C9);
    // ---- conv2: [2048 x 13824] * [1024 x 13824] + C9 -> X2 aug ----
    gemm_mma<128, 128, 2, true><<<dim3(8, 16), 256, SM_BB>>>(
        X1, W2, 1536, 16, 16, 432, 13824, 3, 1024,
        bn2s, bn2h, nullptr, C9, X2, 1024, nullptr, 0);
    // ---- cls1: [2048 x 3072] * [4992 x 3072] -> cls1T fp32 ----
    gemm_mma<128, 128, 2, false><<<dim3(39, 16), 256, SM_BB>>>(
        X2, W3, 3072, 16, 16, 96, 3072, 1, NOUT,
        nullptr, nullptr, c1b, nullptr, nullptr, 0, cls1T, NOUT);
    // ---- c1a: [131072 x 6912] * [48 x 6912] -> c1aT fp32 ----
    gemm_mma<256, 48, 1, true><<<dim3(1, 512), 256, SM_C4>>>(
        Xr2, W4, 768, 128, 128, 216, 6912, 2, 48,
        bn3s, bn3h, nullptr, nullptr, nullptr, 0, c1aT, 48);
    // ---- fused tail ----
    fused_final<<<dim3(256, 8), 256>>>(cls1T, c1aT, bw2, bb2, cats, cath, out);
}

// round 9
// speedup vs baseline: 1.3484x; 1.3484x over previous
#include <cuda_runtime.h>
#include <cuda_bf16.h>
#include <cstdint>

typedef __nv_bfloat16 bf16;
#define NOUT 4928

// ---------------- scratch (device globals; sizes in elements) ----------------
__device__ __align__(16) bf16 g_Xs5[(size_t)2048 * 6144];     // res5 aug [pos][3*2048]
__device__ __align__(16) bf16 g_W1 [(size_t)512 * 55296];     // conv1 W aug
__device__ __align__(16) bf16 g_X1 [(size_t)2048 * 1536];     // x1 aug (moving 512 ch)
__device__ __align__(16) bf16 g_W2 [(size_t)1024 * 13824];    // conv2 W aug
__device__ __align__(16) bf16 g_X2 [(size_t)2048 * 3072];     // x2 aug
__device__ __align__(16) bf16 g_W3 [(size_t)4992 * 3072];     // cls1 W aug (padded)
__device__ __align__(16) bf16 g_Xr2[(size_t)131072 * 768];    // res2 aug
__device__ __align__(16) bf16 g_W4 [(size_t)64 * 6912];       // c1a W aug
__device__ float g_gp [8 * 512];
__device__ float g_C9 [(size_t)8 * 1024 * 9];
__device__ float g_cls1T[(size_t)2048 * NOUT];                // also reused as split-K partials
__device__ float g_c1aT [(size_t)131072 * 48];

// ---------------- helpers ----------------
__device__ __forceinline__ void split2(float v, bf16& h, bf16& l) {
    h = __float2bfloat16(v);
    l = __float2bfloat16(v - __bfloat162float(h));
}
__device__ __forceinline__ unsigned s2u(const void* p) {
    return (unsigned)__cvta_generic_to_shared(p);
}
__device__ __forceinline__ void cpa16(unsigned d, const void* s, unsigned sz) {
    asm volatile("cp.async.ca.shared.global [%0], [%1], 16, %2;" :: "r"(d), "l"(s), "r"(sz));
}
__device__ __forceinline__ void cpa_commit() {
    asm volatile("cp.async.commit_group;" ::: "memory");
}
template<int N> __device__ __forceinline__ void cpa_wait() {
    asm volatile("cp.async.wait_group %0;" :: "n"(N) : "memory");
}
__device__ __forceinline__ void ldm4(unsigned* r, unsigned a) {
    asm volatile("ldmatrix.sync.aligned.m8n8.x4.shared.b16 {%0,%1,%2,%3}, [%4];"
        : "=r"(r[0]), "=r"(r[1]), "=r"(r[2]), "=r"(r[3]) : "r"(a));
}
__device__ __forceinline__ void mma16816(float* d, const unsigned* a, const unsigned* b) {
    asm volatile("mma.sync.aligned.m16n8k16.row.col.f32.bf16.bf16.f32 "
        "{%0,%1,%2,%3}, {%4,%5,%6,%7}, {%8,%9}, {%0,%1,%2,%3};"
        : "+f"(d[0]), "+f"(d[1]), "+f"(d[2]), "+f"(d[3])
        : "r"(a[0]), "r"(a[1]), "r"(a[2]), "r"(a[3]), "r"(b[0]), "r"(b[1]));
}

// =====================================================================
// HMMA GEMM: BK=64, 3-stage cp.async pipeline, 2 CTAs/SM.
// 8 warps as (8/WS) m x WS n.  SMEM row stride 144B (conflict-free).
// epi: 1 = +bias -> fp32 (guarded); 2 = BN+ReLU -> fp32 (guarded);
//      4 = raw fp32 split-K partial at [blockIdx.z][M][ofc]
// =====================================================================
template<int BM, int BN, int WS, bool CONV3>
__global__ __launch_bounds__(256, 2) void gemm_mma(
    const bf16* __restrict__ A, const bf16* __restrict__ B,
    int C3, int imh, int imw, int nk, int Kb,
    int epi, int nvalid,
    const float* __restrict__ scale, const float* __restrict__ shift,
    const float* __restrict__ bias,
    float* __restrict__ Of, int ofc)
{
    constexpr int WM = BM / (8 / WS), WN = BN / WS;
    constexpr int MT = WM / 16;
    constexpr int NT = WN / 8;
    constexpr int NF = WN / 16;
    constexpr int AJ = BM / 32;               // 16B vectors per thread (A)
    constexpr int BJ = (BN * 8 + 255) / 256;  // (B)
    constexpr int ABYTES = BM * 144, STG = (BM + BN) * 144;

    extern __shared__ __align__(16) char sm[];
    const int tid = threadIdx.x;
    const int nb = blockIdx.x, mtile = blockIdx.y;
    const int kzoff = blockIdx.z * nk;
    const int warp = tid >> 5, lane = tid & 31;
    const int m0 = (warp / WS) * WM, n0 = (warp % WS) * WN;
    const unsigned sbase = s2u(sm);
    const int imgpix = imh * imw;
    const int vec = tid & 7;

    int arow[AJ], ay[AJ], ax[AJ], apb[AJ];
#pragma unroll
    for (int j = 0; j < AJ; j++) {
        arow[j] = (tid >> 3) + j * 32;
        int g = mtile * BM + arow[j];
        if (CONV3) {
            int bb = g / imgpix, lp = g - bb * imgpix;
            ay[j] = lp / imw; ax[j] = lp - ay[j] * imw; apb[j] = bb * imgpix;
        } else { ay[j] = 0; ax[j] = 0; apb[j] = g; }
    }

    auto load_chunk = [&](int kc, int st) {
        unsigned Ab = sbase + st * STG;
        unsigned Bb = Ab + ABYTES;
        int k0 = (kzoff + kc) * 64;
        int dy = 0, dx = 0, cb = k0;
        if (CONV3) {
            int rk = k0 / C3; cb = k0 - rk * C3;
            int r3 = rk / 3; dy = r3 - 1; dx = rk - r3 * 3 - 1;
        }
#pragma unroll
        for (int j = 0; j < AJ; j++) {
            const bf16* src;
            unsigned sz = 16;
            if (CONV3) {
                int y2 = ay[j] + dy, x2 = ax[j] + dx;
                bool v = ((unsigned)y2 < (unsigned)imh) && ((unsigned)x2 < (unsigned)imw);
                src = A + (size_t)(apb[j] + y2 * imw + x2) * C3 + cb + vec * 8;
                if (!v) { src = A; sz = 0; }
            } else {
                src = A + (size_t)apb[j] * C3 + k0 + vec * 8;
            }
            cpa16(Ab + arow[j] * 144 + vec * 16, src, sz);
        }
#pragma unroll
        for (int j = 0; j < BJ; j++) {
            int item = tid + 256 * j;
            int row = item >> 3;
            if ((BN * 8 % 256 == 0) || item < BN * 8)
                cpa16(Bb + row * 144 + (item & 7) * 16,
                      B + (size_t)(nb * BN + row) * Kb + k0 + (item & 7) * 8, 16);
        }
    };

    float acc[MT][NT][4];
#pragma unroll
    for (int a = 0; a < MT; a++)
#pragma unroll
        for (int b2 = 0; b2 < NT; b2++)
#pragma unroll
            for (int c = 0; c < 4; c++) acc[a][b2][c] = 0.f;

    auto compute = [&](int st) {
        unsigned Ab = sbase + st * STG;
        unsigned Bb = Ab + ABYTES;
#pragma unroll
        for (int step = 0; step < 4; step++) {
            unsigned af[MT][4], bfr[NF][4];
            {
                int ch = step * 2 + (lane >> 4);
#pragma unroll
                for (int i = 0; i < MT; i++)
                    ldm4(af[i], Ab + (m0 + 16 * i + (lane & 15)) * 144 + ch * 16);
            }
            {
                int rr = (lane & 7) + ((lane >> 4) << 3);
                int ch = step * 2 + ((lane >> 3) & 1);
#pragma unroll
                for (int i = 0; i < NF; i++)
                    ldm4(bfr[i], Bb + (n0 + 16 * i + rr) * 144 + ch * 16);
            }
#pragma unroll
            for (int mt = 0; mt < MT; mt++)
#pragma unroll
                for (int nt = 0; nt < NT; nt++)
                    mma16816(acc[mt][nt], af[mt], &bfr[nt >> 1][(nt & 1) * 2]);
        }
    };

    load_chunk(0, 0);
    cpa_commit();
    if (nk > 1) load_chunk(1, 1);
    cpa_commit();
    int st2 = 2;
    for (int kc = 0; kc < nk; kc++) {
        cpa_wait<1>();
        __syncthreads();
        if (kc + 2 < nk) {
            load_chunk(kc + 2, st2);
            if (++st2 == 3) st2 = 0;
        }
        cpa_commit();
        compute(kc % 3);
    }

    // ---- epilogue ----
    float* dstz = Of;
    if (epi == 4)
        dstz = Of + (size_t)blockIdx.z * ((size_t)gridDim.y * BM) * ofc;
#pragma unroll
    for (int mt = 0; mt < MT; mt++)
#pragma unroll
        for (int nt = 0; nt < NT; nt++) {
            float* d = acc[mt][nt];
            int row = mtile * BM + m0 + mt * 16 + (lane >> 2);
            int col = nb * BN + n0 + nt * 8 + (lane & 3) * 2;
#pragma unroll
            for (int h = 0; h < 2; h++) {
                int r = row + h * 8;
                float v0 = d[h * 2 + 0], v1 = d[h * 2 + 1];
                if (epi == 4) {
                    *(float2*)(dstz + (size_t)r * ofc + col) = make_float2(v0, v1);
                } else if (epi == 1) {
                    if (col < nvalid) {
                        float2 o = make_float2(v0 + bias[col], v1 + bias[col + 1]);
                        *(float2*)(Of + (size_t)r * ofc + col) = o;
                    }
                } else {
                    if (col < nvalid) {
                        float2 o;
                        o.x = fmaxf(fmaf(v0, scale[col], shift[col]), 0.f);
                        o.y = fmaxf(fmaf(v1, scale[col + 1], shift[col + 1]), 0.f);
                        *(float2*)(Of + (size_t)r * ofc + col) = o;
                    }
                }
            }
        }
}

// ---------------- reduce split-K partials + (opt C9) + BN/ReLU -> aug bf16 ----------------
__global__ __launch_bounds__(256) void reduce_aug(
    const float* __restrict__ P, int ns, int M, int C,
    const float* __restrict__ corr,
    const float* __restrict__ scale, const float* __restrict__ shift,
    bf16* __restrict__ out)
{
    int idx = blockIdx.x * 256 + threadIdx.x;
    int r = idx / C, col = idx - r * C;
    if (r >= M) return;
    float v = 0.f;
    for (int s = 0; s < ns; s++) v += P[((size_t)s * M + r) * C + col];
    if (corr) {
        int lp = r & 255, y = lp >> 4, xp = lp & 15;
        int cls = ((y == 0) ? 0 : ((y == 15) ? 6 : 3))
                + ((xp == 0) ? 0 : ((xp == 15) ? 2 : 1));
        v += corr[((size_t)(r >> 8) * 1024 + col) * 9 + cls];
    }
    v = fmaxf(fmaf(v, scale[col], shift[col]), 0.f);
    bf16 h, l; split2(v, h, l);
    size_t base = (size_t)r * 3 * C + col;
    out[base] = h; out[base + C] = l; out[base + 2 * C] = h;
}

// ---------------- prep: NCHW fp32 -> [pos][3C] augmented bf16 ----------------
__global__ __launch_bounds__(256) void split_aug(
    const float* __restrict__ in, bf16* __restrict__ out, int C, int HW)
{
    __shared__ float t[32][33];
    const int b = blockIdx.z, c0 = blockIdx.y * 32, p0 = blockIdx.x * 32;
    const int tx = threadIdx.x & 31, ty = threadIdx.x >> 5;
#pragma unroll
    for (int r = 0; r < 4; r++)
        t[ty + 8 * r][tx] = in[((size_t)b * C + c0 + ty + 8 * r) * HW + p0 + tx];
    __syncthreads();
#pragma unroll
    for (int r = 0; r < 4; r++) {
        int p = p0 + ty + 8 * r;
        float v = t[tx][ty + 8 * r];
        bf16 h, l; split2(v, h, l);
        size_t o = ((size_t)b * HW + p) * 3 * C + c0 + tx;
        out[o] = h; out[o + C] = l; out[o + 2 * C] = h;
    }
}

// ---------------- prep: conv1 weight OIHW -> [oc][tap][3C] augmented ----------------
__global__ __launch_bounds__(256) void wsplit_conv_aug(
    const float* __restrict__ w, bf16* __restrict__ out, int C, int OC)
{
    int idx = blockIdx.x * 256 + threadIdx.x;
    int oc = idx / (9 * C); int rem = idx - oc * 9 * C;
    int tap = rem / C; int c = rem - tap * C;
    float v = (oc < OC) ? w[((size_t)oc * C + c) * 9 + tap] : 0.f;
    bf16 h, l; split2(v, h, l);
    size_t base = (size_t)oc * (27 * C) + (size_t)tap * 3 * C;
    out[base + c] = h; out[base + C + c] = h; out[base + 2 * C + c] = l;
}

// ---------------- prep: conv2 weight, moving cin 0..511 only ----------------
__global__ __launch_bounds__(256) void wsplit_conv2(
    const float* __restrict__ w, bf16* __restrict__ out)
{
    int idx = blockIdx.x * 256 + threadIdx.x;   // 1024 * 9 * 512
    int oc = idx / (9 * 512); int rem = idx - oc * 9 * 512;
    int tap = rem / 512; int c = rem - tap * 512;
    float v = w[((size_t)oc * 1024 + c) * 9 + tap];
    bf16 h, l; split2(v, h, l);
    size_t base = (size_t)oc * 13824 + (size_t)tap * 1536;
    out[base + c] = h; out[base + 512 + c] = h; out[base + 1024 + c] = l;
}

// ---------------- merged small prep: c1a W aug + cls1 W aug ----------------
__global__ __launch_bounds__(256) void wsplit_small(
    const float* __restrict__ aw, const float* __restrict__ c1w,
    bf16* __restrict__ W4, bf16* __restrict__ W3)
{
    const int N4 = 64 * 9 * 256;
    int idx = blockIdx.x * 256 + threadIdx.x;
    if (idx < N4) {
        int oc = idx / (9 * 256); int rem = idx - oc * 9 * 256;
        int tap = rem / 256; int c = rem - tap * 256;
        float v = (oc < 48) ? aw[((size_t)oc * 256 + c) * 9 + tap] : 0.f;
        bf16 h, l; split2(v, h, l);
        size_t base = (size_t)oc * (27 * 256) + (size_t)tap * 768;
        W4[base + c] = h; W4[base + 256 + c] = h; W4[base + 512 + c] = l;
    } else {
        int i2 = idx - N4;
        if (i2 < 4992 * 1024) {
            int oc = i2 >> 10, c = i2 & 1023;
            float v = (oc < NOUT) ? c1w[(size_t)oc * 1024 + c] : 0.f;
            bf16 h, l; split2(v, h, l);
            size_t base = (size_t)oc * 3072;
            W3[base + c] = h; W3[base + 1024 + c] = h; W3[base + 2048 + c] = l;
        }
    }
}

// ---------------- gp reduce over X1 aug (h+l), deterministic ----------------
__global__ __launch_bounds__(512) void gp_reduce(
    const bf16* __restrict__ X1, float* __restrict__ gp)
{
    const int b = blockIdx.x, c = threadIdx.x;    // c in [0,512)
    float s = 0.f;
    for (int p = 0; p < 256; p++) {
        size_t i = ((size_t)(b * 256 + p)) * 1536 + c;
        s += __bfloat162float(X1[i]) + __bfloat162float(X1[i + 512]);
    }
    gp[b * 512 + c] = s * (1.f / 256.f);
}

// ---------------- C9: per-(b, oc, boundary-class) gp correction ----------------
__global__ __launch_bounds__(128) void c9_kernel(
    const float* __restrict__ w, const float* __restrict__ gp, float* __restrict__ C9)
{
    __shared__ float sgp[512];
    __shared__ float sT[16][9];
    const int b = blockIdx.y, oc0 = blockIdx.x * 16, tid = threadIdx.x;
    for (int i = tid; i < 512; i += 128) sgp[i] = gp[b * 512 + i];
    __syncthreads();

    const int oc = oc0 + (tid >> 3), ln = tid & 7;
    float t[9];
#pragma unroll
    for (int k = 0; k < 9; k++) t[k] = 0.f;
    for (int c = ln * 64; c < ln * 64 + 64; c++) {
        float g = sgp[c];
        const float* wp = w + ((size_t)oc * 1024 + 512 + c) * 9;
#pragma unroll
        for (int k = 0; k < 9; k++) t[k] = fmaf(wp[k], g, t[k]);
    }
#pragma unroll
    for (int o = 4; o; o >>= 1)
#pragma unroll
        for (int k = 0; k < 9; k++) t[k] += __shfl_down_sync(0xffffffffu, t[k], o, 8);
    if (ln == 0)
#pragma unroll
        for (int k = 0; k < 9; k++) sT[tid >> 3][k] = t[k];
    __syncthreads();

    for (int i = tid; i < 144; i += 128) {
        int o = i / 9, cls = i - (i / 9) * 9;
        int fy = cls / 3, fx = cls - fy * 3;
        float s = 0.f;
#pragma unroll
        for (int ky = 0; ky < 3; ky++) {
            if ((fy == 0 && ky == 0) || (fy == 2 && ky == 2)) continue;
#pragma unroll
            for (int kx = 0; kx < 3; kx++) {
                if ((fx == 0 && kx == 0) || (fx == 2 && kx == 2)) continue;
                s += sT[o][ky * 3 + kx];
            }
        }
        C9[((size_t)b * 1024 + oc0 + o) * 9 + cls] = s;
    }
}

// ---------------- fused: c1b + coord + cat-BN + 3-layer dynamic MLP ----------------
__global__ __launch_bounds__(256) void fused_final(
    const float* __restrict__ cls1T, const float* __restrict__ c1aT,
    const float* __restrict__ c1b_w, const float* __restrict__ c1b_b,
    const float* __restrict__ cat_scale, const float* __restrict__ cat_shift,
    float* __restrict__ out)
{
    const int b = blockIdx.y, lpos = blockIdx.x;
    const int ly = lpos >> 4, lx = lpos & 15;
    const int tid = threadIdx.x;
    const int px = tid & 63, q = tid >> 6;
    const int py = px >> 3, pxx = px & 7;

    __shared__ float sP[NOUT];
    __shared__ float sA[48 * 64];
    __shared__ float sI[18 * 64];
    __shared__ float sH0[16 * 64];
    __shared__ float sH1[16 * 64];
    __shared__ float sWb[768 + 16];

    const float* pp = cls1T + (size_t)(b * 256 + lpos) * NOUT;
    for (int i = tid; i < NOUT; i += 256) sP[i] = pp[i];
    for (int i = tid; i < 48 * 64; i += 256) {
        int p = i / 48, ch = i - p * 48;
        int yy = ly * 8 + (p >> 3), xx = lx * 8 + (p & 7);
        sA[ch * 64 + p] = c1aT[((size_t)b * 16384 + yy * 128 + xx) * 48 + ch];
    }
    for (int i = tid; i < 768; i += 256) sWb[i] = c1b_w[i];
    if (tid < 16) sWb[768 + tid] = c1b_b[tid];
    __syncthreads();

#pragma unroll
    for (int jj = 0; jj < 4; jj++) {
        int j = q * 4 + jj;
        float s = sWb[768 + j];
#pragma unroll
        for (int c = 0; c < 48; c++)
            s = fmaf(sA[c * 64 + px], sWb[j * 48 + c], s);
        sI[(2 + j) * 64 + px] = fmaf(s, cat_scale[2 + j], cat_shift[2 + j]);
    }
    if (q == 0) {
        sI[px]      = fmaf((float)pxx * 0.125f, cat_scale[0], cat_shift[0]);
        sI[64 + px] = fmaf((float)py  * 0.125f, cat_scale[1], cat_shift[1]);
    }
    __syncthreads();

#pragma unroll
    for (int jj = 0; jj < 4; jj++) {
        int o = q * 4 + jj;
        float s = sP[288 + o];
#pragma unroll
        for (int c = 0; c < 18; c++)
            s = fmaf(sP[o * 18 + c], sI[c * 64 + px], s);
        sH0[o * 64 + px] = fmaxf(s, 0.f);
    }
    __syncthreads();

#pragma unroll
    for (int jj = 0; jj < 4; jj++) {
        int o = q * 4 + jj;
        float s = sP[560 + o];
#pragma unroll
        for (int c = 0; c < 16; c++)
            s = fmaf(sP[304 + o * 16 + c], sH0[c * 64 + px], s);
        sH1[o * 64 + px] = fmaxf(s, 0.f);
    }
    __syncthreads();

    float hr[16];
#pragma unroll
    for (int c = 0; c < 16; c++) hr[c] = sH1[c * 64 + px];
    const int y = ly * 8 + py, x = lx * 8 + pxx;
    float* ob = out + (((size_t)b * 256) << 14) + (y << 7) + x;
#pragma unroll 4
    for (int oo = 0; oo < 64; oo++) {
        int o = q * 64 + oo;
        float s = sP[4672 + o];
#pragma unroll
        for (int c = 0; c < 16; c++)
            s = fmaf(sP[576 + o * 16 + c], hr[c], s);
        ob[(size_t)o << 14] = s;
    }
}

// ---------------- host launcher ----------------
extern "C" void kernel_launch(void* const* d_in, const int* in_sizes, int n_in,
                              void* d_out, int out_size)
{
    const float* res5 = (const float*)d_in[0];
    const float* res2 = (const float*)d_in[1];
    const float* bw   = (const float*)d_in[2];
    const float* bn1s = (const float*)d_in[3];
    const float* bn1h = (const float*)d_in[4];
    const float* c0w  = (const float*)d_in[5];
    const float* bn2s = (const float*)d_in[6];
    const float* bn2h = (const float*)d_in[7];
    const float* c1w  = (const float*)d_in[8];
    const float* c1b  = (const float*)d_in[9];
    const float* aw   = (const float*)d_in[10];
    const float* bn3s = (const float*)d_in[11];
    const float* bn3h = (const float*)d_in[12];
    const float* bw2  = (const float*)d_in[13];
    const float* bb2  = (const float*)d_in[14];
    const float* cats = (const float*)d_in[15];
    const float* cath = (const float*)d_in[16];
    float* out = (float*)d_out;

    bf16 *Xs5, *W1, *X1, *W2, *X2, *W3, *Xr2, *W4;
    float *gp, *C9, *cls1T, *c1aT;
    cudaGetSymbolAddress((void**)&Xs5, g_Xs5);
    cudaGetSymbolAddress((void**)&W1,  g_W1);
    cudaGetSymbolAddress((void**)&X1,  g_X1);
    cudaGetSymbolAddress((void**)&W2,  g_W2);
    cudaGetSymbolAddress((void**)&X2,  g_X2);
    cudaGetSymbolAddress((void**)&W3,  g_W3);
    cudaGetSymbolAddress((void**)&Xr2, g_Xr2);
    cudaGetSymbolAddress((void**)&W4,  g_W4);
    cudaGetSymbolAddress((void**)&gp,  g_gp);
    cudaGetSymbolAddress((void**)&C9,  g_C9);
    cudaGetSymbolAddress((void**)&cls1T, g_cls1T);
    cudaGetSymbolAddress((void**)&c1aT,  g_c1aT);

    const int SM_C1 = (128 + 64) * 144 * 3;    // 82944
    const int SM_BB = (128 + 128) * 144 * 3;   // 110592
    const int SM_C4 = (128 + 48) * 144 * 3;    // 76032
    cudaFuncSetAttribute(gemm_mma<128, 64, 2, true>,   cudaFuncAttributeMaxDynamicSharedMemorySize, SM_C1);
    cudaFuncSetAttribute(gemm_mma<128, 128, 2, true>,  cudaFuncAttributeMaxDynamicSharedMemorySize, SM_BB);
    cudaFuncSetAttribute(gemm_mma<128, 128, 2, false>, cudaFuncAttributeMaxDynamicSharedMemorySize, SM_BB);
    cudaFuncSetAttribute(gemm_mma<128, 48, 1, true>,   cudaFuncAttributeMaxDynamicSharedMemorySize, SM_C4);

    // 1) res5 -> aug
    split_aug<<<dim3(8, 64, 8), 256>>>(res5, Xs5, 2048, 256);
    // 2) conv1 weights -> aug
    wsplit_conv_aug<<<(512 * 9 * 2048) / 256, 256>>>(bw, W1, 2048, 512);
    // 3) conv1 GEMM, split-K x3 -> partials in cls1T
    gemm_mma<128, 64, 2, true><<<dim3(8, 16, 3), 256, SM_C1>>>(
        Xs5, W1, 6144, 16, 16, 288, 55296, 4, 512,
        nullptr, nullptr, nullptr, cls1T, 512);
    // 4) reduce -> X1 aug
    reduce_aug<<<(2048 * 512) / 256, 256>>>(cls1T, 3, 2048, 512, nullptr, bn1s, bn1h, X1);
    // 5) global pool
    gp_reduce<<<8, 512>>>(X1, gp);
    // 6) C9 correction table
    c9_kernel<<<dim3(64, 8), 128>>>(c0w, gp, C9);
    // 7) conv2 weights -> aug
    wsplit_conv2<<<(1024 * 9 * 512) / 256, 256>>>(c0w, W2);
    // 8) conv2 GEMM, split-K x2 -> partials in cls1T
    gemm_mma<128, 128, 2, true><<<dim3(8, 16, 2), 256, SM_BB>>>(
        X1, W2, 1536, 16, 16, 108, 13824, 4, 1024,
        nullptr, nullptr, nullptr, cls1T, 1024);
    // 9) reduce (+C9) -> X2 aug
    reduce_aug<<<(2048 * 1024) / 256, 256>>>(cls1T, 2, 2048, 1024, C9, bn2s, bn2h, X2);
    // 10) small weights -> aug
    wsplit_small<<<(64 * 9 * 256 + 4992 * 1024 + 255) / 256, 256>>>(aw, c1w, W4, W3);
    // 11) cls1 GEMM -> cls1T fp32
    gemm_mma<128, 128, 2, false><<<dim3(39, 16, 1), 256, SM_BB>>>(
        X2, W3, 3072, 16, 16, 48, 3072, 1, NOUT,
        nullptr, nullptr, c1b, cls1T, NOUT);
    // 12) res2 -> aug
    split_aug<<<dim3(512, 8, 8), 256>>>(res2, Xr2, 256, 16384);
    // 13) c1a GEMM -> c1aT fp32
    gemm_mma<128, 48, 1, true><<<dim3(1, 1024, 1), 256, SM_C4>>>(
        Xr2, W4, 768, 128, 128, 108, 6912, 2, 48,
        bn3s, bn3h, nullptr, c1aT, 48);
    // 14) fused tail
    fused_final<<<dim3(256, 8), 256>>>(cls1T, c1aT, bw2, bb2, cats, cath, out);
}

// round 10
// speedup vs baseline: 1.7805x; 1.3204x over previous
#include <cuda_runtime.h>
#include <cuda_fp16.h>
#include <cstdint>

typedef __half h16;
#define NOUT 4928

// ---------------- scratch (device globals; sizes in elements) ----------------
__device__ __align__(16) h16 g_Xs5[(size_t)2048 * 4096];     // res5 aug [pos][h(2048)|l(2048)]
__device__ __align__(16) h16 g_W1 [(size_t)512 * 36864];     // conv1 W aug [oc][9][wh|wh]
__device__ __align__(16) h16 g_X1 [(size_t)2048 * 1024];     // x1 aug [pos][h(512)|l(512)]
__device__ __align__(16) h16 g_W2 [(size_t)1024 * 9216];     // conv2 W aug (moving 512 cin)
__device__ __align__(16) h16 g_X2 [(size_t)2048 * 2048];     // x2 aug
__device__ __align__(16) h16 g_W3 [(size_t)4992 * 2048];     // cls1 W aug (oc padded)
__device__ __align__(16) h16 g_Xr2[(size_t)131072 * 512];    // res2 aug
__device__ __align__(16) h16 g_W4 [(size_t)64 * 4608];       // c1a W aug
__device__ float g_gp [8 * 512];
__device__ float g_C9 [(size_t)8 * 1024 * 9];
__device__ float g_cls1T[(size_t)2048 * NOUT];               // also split-K partial buffer
__device__ float g_c1aT [(size_t)131072 * 48];

// ---------------- helpers ----------------
__device__ __forceinline__ void split2h(float v, h16& h, h16& l) {
    h = __float2half_rn(v);
    l = __float2half_rn(v - __half2float(h));
}
__device__ __forceinline__ unsigned s2u(const void* p) {
    return (unsigned)__cvta_generic_to_shared(p);
}
__device__ __forceinline__ void cpa16(unsigned d, const void* s, unsigned sz) {
    asm volatile("cp.async.ca.shared.global [%0], [%1], 16, %2;" :: "r"(d), "l"(s), "r"(sz));
}
__device__ __forceinline__ void cpa_commit() {
    asm volatile("cp.async.commit_group;" ::: "memory");
}
template<int N> __device__ __forceinline__ void cpa_wait() {
    asm volatile("cp.async.wait_group %0;" :: "n"(N) : "memory");
}
__device__ __forceinline__ void ldm4(unsigned* r, unsigned a) {
    asm volatile("ldmatrix.sync.aligned.m8n8.x4.shared.b16 {%0,%1,%2,%3}, [%4];"
        : "=r"(r[0]), "=r"(r[1]), "=r"(r[2]), "=r"(r[3]) : "r"(a));
}
__device__ __forceinline__ void mma16816(float* d, const unsigned* a, const unsigned* b) {
    asm volatile("mma.sync.aligned.m16n8k16.row.col.f32.f16.f16.f32 "
        "{%0,%1,%2,%3}, {%4,%5,%6,%7}, {%8,%9}, {%0,%1,%2,%3};"
        : "+f"(d[0]), "+f"(d[1]), "+f"(d[2]), "+f"(d[3])
        : "r"(a[0]), "r"(a[1]), "r"(a[2]), "r"(a[3]), "r"(b[0]), "r"(b[1]));
}

// =====================================================================
// HMMA fp16 GEMM: BK=64, 3-stage cp.async pipeline, 2 CTAs/SM.
// 8 warps as (8/WS) m x WS n.  SMEM row stride 144B (conflict-free).
// epi: 1 = +bias -> fp32 (guarded); 2 = BN+ReLU -> fp32 (guarded);
//      4 = raw fp32 split-K partial at [blockIdx.z][M][ofc]
// =====================================================================
template<int BM, int BN, int WS, bool CONV3>
__global__ __launch_bounds__(256, 2) void gemm_mma(
    const h16* __restrict__ A, const h16* __restrict__ B,
    int C3, int imh, int imw, int nk, int Kb,
    int epi, int nvalid,
    const float* __restrict__ scale, const float* __restrict__ shift,
    const float* __restrict__ bias,
    float* __restrict__ Of, int ofc)
{
    constexpr int WM = BM / (8 / WS), WN = BN / WS;
    constexpr int MT = WM / 16;
    constexpr int NT = WN / 8;
    constexpr int NF = WN / 16;
    constexpr int AJ = BM / 32;
    constexpr int BJ = (BN * 8 + 255) / 256;
    constexpr int ABYTES = BM * 144, STG = (BM + BN) * 144;

    extern __shared__ __align__(16) char sm[];
    const int tid = threadIdx.x;
    const int nb = blockIdx.x, mtile = blockIdx.y;
    const int kzoff = blockIdx.z * nk;
    const int warp = tid >> 5, lane = tid & 31;
    const int m0 = (warp / WS) * WM, n0 = (warp % WS) * WN;
    const unsigned sbase = s2u(sm);
    const int imgpix = imh * imw;
    const int vec = tid & 7;

    int arow[AJ], ay[AJ], ax[AJ], apb[AJ];
#pragma unroll
    for (int j = 0; j < AJ; j++) {
        arow[j] = (tid >> 3) + j * 32;
        int g = mtile * BM + arow[j];
        if (CONV3) {
            int bb = g / imgpix, lp = g - bb * imgpix;
            ay[j] = lp / imw; ax[j] = lp - ay[j] * imw; apb[j] = bb * imgpix;
        } else { ay[j] = 0; ax[j] = 0; apb[j] = g; }
    }

    auto load_chunk = [&](int kc, int st) {
        unsigned Ab = sbase + st * STG;
        unsigned Bb = Ab + ABYTES;
        int k0 = (kzoff + kc) * 64;
        int dy = 0, dx = 0, cb = k0;
        if (CONV3) {
            int rk = k0 / C3; cb = k0 - rk * C3;
            int r3 = rk / 3; dy = r3 - 1; dx = rk - r3 * 3 - 1;
        }
#pragma unroll
        for (int j = 0; j < AJ; j++) {
            const h16* src;
            unsigned sz = 16;
            if (CONV3) {
                int y2 = ay[j] + dy, x2 = ax[j] + dx;
                bool v = ((unsigned)y2 < (unsigned)imh) && ((unsigned)x2 < (unsigned)imw);
                src = A + (size_t)(apb[j] + y2 * imw + x2) * C3 + cb + vec * 8;
                if (!v) { src = A; sz = 0; }
            } else {
                src = A + (size_t)apb[j] * C3 + k0 + vec * 8;
            }
            cpa16(Ab + arow[j] * 144 + vec * 16, src, sz);
        }
#pragma unroll
        for (int j = 0; j < BJ; j++) {
            int item = tid + 256 * j;
            int row = item >> 3;
            if ((BN * 8 % 256 == 0) || item < BN * 8)
                cpa16(Bb + row * 144 + (item & 7) * 16,
                      B + (size_t)(nb * BN + row) * Kb + k0 + (item & 7) * 8, 16);
        }
    };

    float acc[MT][NT][4];
#pragma unroll
    for (int a = 0; a < MT; a++)
#pragma unroll
        for (int b2 = 0; b2 < NT; b2++)
#pragma unroll
            for (int c = 0; c < 4; c++) acc[a][b2][c] = 0.f;

    auto compute = [&](int st) {
        unsigned Ab = sbase + st * STG;
        unsigned Bb = Ab + ABYTES;
#pragma unroll
        for (int step = 0; step < 4; step++) {
            unsigned af[MT][4], bfr[NF][4];
            {
                int ch = step * 2 + (lane >> 4);
#pragma unroll
                for (int i = 0; i < MT; i++)
                    ldm4(af[i], Ab + (m0 + 16 * i + (lane & 15)) * 144 + ch * 16);
            }
            {
                int rr = (lane & 7) + ((lane >> 4) << 3);
                int ch = step * 2 + ((lane >> 3) & 1);
#pragma unroll
                for (int i = 0; i < NF; i++)
                    ldm4(bfr[i], Bb + (n0 + 16 * i + rr) * 144 + ch * 16);
            }
#pragma unroll
            for (int mt = 0; mt < MT; mt++)
#pragma unroll
                for (int nt = 0; nt < NT; nt++)
                    mma16816(acc[mt][nt], af[mt], &bfr[nt >> 1][(nt & 1) * 2]);
        }
    };

    load_chunk(0, 0);
    cpa_commit();
    if (nk > 1) load_chunk(1, 1);
    cpa_commit();
    int st2 = 2;
    for (int kc = 0; kc < nk; kc++) {
        cpa_wait<1>();
        __syncthreads();
        if (kc + 2 < nk) {
            load_chunk(kc + 2, st2);
            if (++st2 == 3) st2 = 0;
        }
        cpa_commit();
        compute(kc % 3);
    }

    // ---- epilogue ----
    float* dstz = Of;
    if (epi == 4)
        dstz = Of + (size_t)blockIdx.z * ((size_t)gridDim.y * BM) * ofc;
#pragma unroll
    for (int mt = 0; mt < MT; mt++)
#pragma unroll
        for (int nt = 0; nt < NT; nt++) {
            float* d = acc[mt][nt];
            int row = mtile * BM + m0 + mt * 16 + (lane >> 2);
            int col = nb * BN + n0 + nt * 8 + (lane & 3) * 2;
#pragma unroll
            for (int h = 0; h < 2; h++) {
                int r = row + h * 8;
                float v0 = d[h * 2 + 0], v1 = d[h * 2 + 1];
                if (epi == 4) {
                    *(float2*)(dstz + (size_t)r * ofc + col) = make_float2(v0, v1);
                } else if (epi == 1) {
                    if (col < nvalid) {
                        float2 o = make_float2(v0 + bias[col], v1 + bias[col + 1]);
                        *(float2*)(Of + (size_t)r * ofc + col) = o;
                    }
                } else {
                    if (col < nvalid) {
                        float2 o;
                        o.x = fmaxf(fmaf(v0, scale[col], shift[col]), 0.f);
                        o.y = fmaxf(fmaf(v1, scale[col + 1], shift[col + 1]), 0.f);
                        *(float2*)(Of + (size_t)r * ofc + col) = o;
                    }
                }
            }
        }
}

// ---------------- reduce split-K partials + (opt C9) + BN/ReLU -> aug fp16 ----------------
__global__ __launch_bounds__(256) void reduce_aug(
    const float* __restrict__ P, int ns, int M, int C,
    const float* __restrict__ corr,
    const float* __restrict__ scale, const float* __restrict__ shift,
    h16* __restrict__ out)
{
    int idx = blockIdx.x * 256 + threadIdx.x;
    int r = idx / C, col = idx - r * C;
    if (r >= M) return;
    float v = 0.f;
    for (int s = 0; s < ns; s++) v += P[((size_t)s * M + r) * C + col];
    if (corr) {
        int lp = r & 255, y = lp >> 4, xp = lp & 15;
        int cls = ((y == 0) ? 0 : ((y == 15) ? 6 : 3))
                + ((xp == 0) ? 0 : ((xp == 15) ? 2 : 1));
        v += corr[((size_t)(r >> 8) * 1024 + col) * 9 + cls];
    }
    v = fmaxf(fmaf(v, scale[col], shift[col]), 0.f);
    h16 h, l; split2h(v, h, l);
    size_t base = (size_t)r * 2 * C + col;
    out[base] = h; out[base + C] = l;
}

// ---------------- prep: NCHW fp32 -> [pos][h(C)|l(C)] fp16 ----------------
__global__ __launch_bounds__(256) void split_aug(
    const float* __restrict__ in, h16* __restrict__ out, int C, int HW)
{
    __shared__ float t[32][33];
    const int b = blockIdx.z, c0 = blockIdx.y * 32, p0 = blockIdx.x * 32;
    const int tx = threadIdx.x & 31, ty = threadIdx.x >> 5;
#pragma unroll
    for (int r = 0; r < 4; r++)
        t[ty + 8 * r][tx] = in[((size_t)b * C + c0 + ty + 8 * r) * HW + p0 + tx];
    __syncthreads();
#pragma unroll
    for (int r = 0; r < 4; r++) {
        int p = p0 + ty + 8 * r;
        float v = t[tx][ty + 8 * r];
        h16 h, l; split2h(v, h, l);
        size_t o = ((size_t)b * HW + p) * 2 * C + c0 + tx;
        out[o] = h; out[o + C] = l;
    }
}

// ---------------- prep: conv1 weight OIHW -> [oc][tap][wh|wh] ----------------
__global__ __launch_bounds__(256) void wsplit_conv_aug(
    const float* __restrict__ w, h16* __restrict__ out, int C, int OC)
{
    int idx = blockIdx.x * 256 + threadIdx.x;
    int oc = idx / (9 * C); int rem = idx - oc * 9 * C;
    int tap = rem / C; int c = rem - tap * C;
    float v = (oc < OC) ? w[((size_t)oc * C + c) * 9 + tap] : 0.f;
    h16 h = __float2half_rn(v);
    size_t base = (size_t)oc * (18 * C) + (size_t)tap * 2 * C;
    out[base + c] = h; out[base + C + c] = h;
}

// ---------------- prep: conv2 weight, moving cin 0..511 only ----------------
__global__ __launch_bounds__(256) void wsplit_conv2(
    const float* __restrict__ w, h16* __restrict__ out)
{
    int idx = blockIdx.x * 256 + threadIdx.x;   // 1024 * 9 * 512
    int oc = idx / (9 * 512); int rem = idx - oc * 9 * 512;
    int tap = rem / 512; int c = rem - tap * 512;
    h16 h = __float2half_rn(w[((size_t)oc * 1024 + c) * 9 + tap]);
    size_t base = (size_t)oc * 9216 + (size_t)tap * 1024;
    out[base + c] = h; out[base + 512 + c] = h;
}

// ---------------- merged small prep: c1a W aug + cls1 W aug ----------------
__global__ __launch_bounds__(256) void wsplit_small(
    const float* __restrict__ aw, const float* __restrict__ c1w,
    h16* __restrict__ W4, h16* __restrict__ W3)
{
    const int N4 = 64 * 9 * 256;
    int idx = blockIdx.x * 256 + threadIdx.x;
    if (idx < N4) {
        int oc = idx / (9 * 256); int rem = idx - oc * 9 * 256;
        int tap = rem / 256; int c = rem - tap * 256;
        float v = (oc < 48) ? aw[((size_t)oc * 256 + c) * 9 + tap] : 0.f;
        h16 h = __float2half_rn(v);
        size_t base = (size_t)oc * 4608 + (size_t)tap * 512;
        W4[base + c] = h; W4[base + 256 + c] = h;
    } else {
        int i2 = idx - N4;
        if (i2 < 4992 * 1024) {
            int oc = i2 >> 10, c = i2 & 1023;
            float v = (oc < NOUT) ? c1w[(size_t)oc * 1024 + c] : 0.f;
            h16 h = __float2half_rn(v);
            size_t base = (size_t)oc * 2048;
            W3[base + c] = h; W3[base + 1024 + c] = h;
        }
    }
}

// ---------------- gp reduce over X1 aug (h+l), deterministic ----------------
__global__ __launch_bounds__(512) void gp_reduce(
    const h16* __restrict__ X1, float* __restrict__ gp)
{
    const int b = blockIdx.x, c = threadIdx.x;    // c in [0,512)
    float s = 0.f;
    for (int p = 0; p < 256; p++) {
        size_t i = ((size_t)(b * 256 + p)) * 1024 + c;
        s += __half2float(X1[i]) + __half2float(X1[i + 512]);
    }
    gp[b * 512 + c] = s * (1.f / 256.f);
}

// ---------------- C9: per-(b, oc, boundary-class) gp correction ----------------
__global__ __launch_bounds__(128) void c9_kernel(
    const float* __restrict__ w, const float* __restrict__ gp, float* __restrict__ C9)
{
    __shared__ float sgp[512];
    __shared__ float sT[16][9];
    const int b = blockIdx.y, oc0 = blockIdx.x * 16, tid = threadIdx.x;
    for (int i = tid; i < 512; i += 128) sgp[i] = gp[b * 512 + i];
    __syncthreads();

    const int oc = oc0 + (tid >> 3), ln = tid & 7;
    float t[9];
#pragma unroll
    for (int k = 0; k < 9; k++) t[k] = 0.f;
    for (int c = ln * 64; c < ln * 64 + 64; c++) {
        float g = sgp[c];
        const float* wp = w + ((size_t)oc * 1024 + 512 + c) * 9;
#pragma unroll
        for (int k = 0; k < 9; k++) t[k] = fmaf(wp[k], g, t[k]);
    }
#pragma unroll
    for (int o = 4; o; o >>= 1)
#pragma unroll
        for (int k = 0; k < 9; k++) t[k] += __shfl_down_sync(0xffffffffu, t[k], o, 8);
    if (ln == 0)
#pragma unroll
        for (int k = 0; k < 9; k++) sT[tid >> 3][k] = t[k];
    __syncthreads();

    for (int i = tid; i < 144; i += 128) {
        int o = i / 9, cls = i - (i / 9) * 9;
        int fy = cls / 3, fx = cls - fy * 3;
        float s = 0.f;
#pragma unroll
        for (int ky = 0; ky < 3; ky++) {
            if ((fy == 0 && ky == 0) || (fy == 2 && ky == 2)) continue;
#pragma unroll
            for (int kx = 0; kx < 3; kx++) {
                if ((fx == 0 && kx == 0) || (fx == 2 && kx == 2)) continue;
                s += sT[o][ky * 3 + kx];
            }
        }
        C9[((size_t)b * 1024 + oc0 + o) * 9 + cls] = s;
    }
}

// ---------------- fused: c1b + coord + cat-BN + 3-layer dynamic MLP ----------------
__global__ __launch_bounds__(256) void fused_final(
    const float* __restrict__ cls1T, const float* __restrict__ c1aT,
    const float* __restrict__ c1b_w, const float* __restrict__ c1b_b,
    const float* __restrict__ cat_scale, const float* __restrict__ cat_shift,
    float* __restrict__ out)
{
    const int b = blockIdx.y, lpos = blockIdx.x;
    const int ly = lpos >> 4, lx = lpos & 15;
    const int tid = threadIdx.x;
    const int px = tid & 63, q = tid >> 6;
    const int py = px >> 3, pxx = px & 7;

    __shared__ float sP[NOUT];
    __shared__ float sA[48 * 64];
    __shared__ float sI[18 * 64];
    __shared__ float sH0[16 * 64];
    __shared__ float sH1[16 * 64];
    __shared__ float sWb[768 + 16];

    const float* pp = cls1T + (size_t)(b * 256 + lpos) * NOUT;
    for (int i = tid; i < NOUT; i += 256) sP[i] = pp[i];
    for (int i = tid; i < 48 * 64; i += 256) {
        int p = i / 48, ch = i - p * 48;
        int yy = ly * 8 + (p >> 3), xx = lx * 8 + (p & 7);
        sA[ch * 64 + p] = c1aT[((size_t)b * 16384 + yy * 128 + xx) * 48 + ch];
    }
    for (int i = tid; i < 768; i += 256) sWb[i] = c1b_w[i];
    if (tid < 16) sWb[768 + tid] = c1b_b[tid];
    __syncthreads();

#pragma unroll
    for (int jj = 0; jj < 4; jj++) {
        int j = q * 4 + jj;
        float s = sWb[768 + j];
#pragma unroll
        for (int c = 0; c < 48; c++)
            s = fmaf(sA[c * 64 + px], sWb[j * 48 + c], s);
        sI[(2 + j) * 64 + px] = fmaf(s, cat_scale[2 + j], cat_shift[2 + j]);
    }
    if (q == 0) {
        sI[px]      = fmaf((float)pxx * 0.125f, cat_scale[0], cat_shift[0]);
        sI[64 + px] = fmaf((float)py  * 0.125f, cat_scale[1], cat_shift[1]);
    }
    __syncthreads();

#pragma unroll
    for (int jj = 0; jj < 4; jj++) {
        int o = q * 4 + jj;
        float s = sP[288 + o];
#pragma unroll
        for (int c = 0; c < 18; c++)
            s = fmaf(sP[o * 18 + c], sI[c * 64 + px], s);
        sH0[o * 64 + px] = fmaxf(s, 0.f);
    }
    __syncthreads();

#pragma unroll
    for (int jj = 0; jj < 4; jj++) {
        int o = q * 4 + jj;
        float s = sP[560 + o];
#pragma unroll
        for (int c = 0; c < 16; c++)
            s = fmaf(sP[304 + o * 16 + c], sH0[c * 64 + px], s);
        sH1[o * 64 + px] = fmaxf(s, 0.f);
    }
    __syncthreads();

    float hr[16];
#pragma unroll
    for (int c = 0; c < 16; c++) hr[c] = sH1[c * 64 + px];
    const int y = ly * 8 + py, x = lx * 8 + pxx;
    float* ob = out + (((size_t)b * 256) << 14) + (y << 7) + x;
#pragma unroll 4
    for (int oo = 0; oo < 64; oo++) {
        int o = q * 64 + oo;
        float s = sP[4672 + o];
#pragma unroll
        for (int c = 0; c < 16; c++)
            s = fmaf(sP[576 + o * 16 + c], hr[c], s);
        ob[(size_t)o << 14] = s;
    }
}

// ---------------- host launcher ----------------
extern "C" void kernel_launch(void* const* d_in, const int* in_sizes, int n_in,
                              void* d_out, int out_size)
{
    const float* res5 = (const float*)d_in[0];
    const float* res2 = (const float*)d_in[1];
    const float* bw   = (const float*)d_in[2];
    const float* bn1s = (const float*)d_in[3];
    const float* bn1h = (const float*)d_in[4];
    const float* c0w  = (const float*)d_in[5];
    const float* bn2s = (const float*)d_in[6];
    const float* bn2h = (const float*)d_in[7];
    const float* c1w  = (const float*)d_in[8];
    const float* c1b  = (const float*)d_in[9];
    const float* aw   = (const float*)d_in[10];
    const float* bn3s = (const float*)d_in[11];
    const float* bn3h = (const float*)d_in[12];
    const float* bw2  = (const float*)d_in[13];
    const float* bb2  = (const float*)d_in[14];
    const float* cats = (const float*)d_in[15];
    const float* cath = (const float*)d_in[16];
    float* out = (float*)d_out;

    h16 *Xs5, *W1, *X1, *W2, *X2, *W3, *Xr2, *W4;
    float *gp, *C9, *cls1T, *c1aT;
    cudaGetSymbolAddress((void**)&Xs5, g_Xs5);
    cudaGetSymbolAddress((void**)&W1,  g_W1);
    cudaGetSymbolAddress((void**)&X1,  g_X1);
    cudaGetSymbolAddress((void**)&W2,  g_W2);
    cudaGetSymbolAddress((void**)&X2,  g_X2);
    cudaGetSymbolAddress((void**)&W3,  g_W3);
    cudaGetSymbolAddress((void**)&Xr2, g_Xr2);
    cudaGetSymbolAddress((void**)&W4,  g_W4);
    cudaGetSymbolAddress((void**)&gp,  g_gp);
    cudaGetSymbolAddress((void**)&C9,  g_C9);
    cudaGetSymbolAddress((void**)&cls1T, g_cls1T);
    cudaGetSymbolAddress((void**)&c1aT,  g_c1aT);

    const int SM_C1 = (128 + 64) * 144 * 3;    // 82944
    const int SM_BB = (128 + 128) * 144 * 3;   // 110592
    const int SM_C4 = (128 + 48) * 144 * 3;    // 76032
    cudaFuncSetAttribute(gemm_mma<128, 64, 2, true>,   cudaFuncAttributeMaxDynamicSharedMemorySize, SM_C1);
    cudaFuncSetAttribute(gemm_mma<128, 128, 2, true>,  cudaFuncAttributeMaxDynamicSharedMemorySize, SM_BB);
    cudaFuncSetAttribute(gemm_mma<128, 128, 2, false>, cudaFuncAttributeMaxDynamicSharedMemorySize, SM_BB);
    cudaFuncSetAttribute(gemm_mma<128, 48, 1, true>,   cudaFuncAttributeMaxDynamicSharedMemorySize, SM_C4);

    // 1) res5 -> aug
    split_aug<<<dim3(8, 64, 8), 256>>>(res5, Xs5, 2048, 256);
    // 2) conv1 weights -> aug
    wsplit_conv_aug<<<(512 * 9 * 2048) / 256, 256>>>(bw, W1, 2048, 512);
    // 3) conv1 GEMM: K' = 36864, split-K x3 (192 chunks each) -> partials
    gemm_mma<128, 64, 2, true><<<dim3(8, 16, 3), 256, SM_C1>>>(
        Xs5, W1, 4096, 16, 16, 192, 36864, 4, 512,
        nullptr, nullptr, nullptr, cls1T, 512);
    // 4) reduce -> X1 aug
    reduce_aug<<<(2048 * 512) / 256, 256>>>(cls1T, 3, 2048, 512, nullptr, bn1s, bn1h, X1);
    // 5) global pool
    gp_reduce<<<8, 512>>>(X1, gp);
    // 6) C9 correction table
    c9_kernel<<<dim3(64, 8), 128>>>(c0w, gp, C9);
    // 7) conv2 weights -> aug
    wsplit_conv2<<<(1024 * 9 * 512) / 256, 256>>>(c0w, W2);
    // 8) conv2 GEMM: K' = 9216, split-K x2 (72 chunks each)
    gemm_mma<128, 128, 2, true><<<dim3(8, 16, 2), 256, SM_BB>>>(
        X1, W2, 1024, 16, 16, 72, 9216, 4, 1024,
        nullptr, nullptr, nullptr, cls1T, 1024);
    // 9) reduce (+C9) -> X2 aug
    reduce_aug<<<(2048 * 1024) / 256, 256>>>(cls1T, 2, 2048, 1024, C9, bn2s, bn2h, X2);
    // 10) small weights -> aug
    wsplit_small<<<(64 * 9 * 256 + 4992 * 1024 + 255) / 256, 256>>>(aw, c1w, W4, W3);
    // 11) cls1 GEMM: K' = 2048 (32 chunks) -> cls1T fp32
    gemm_mma<128, 128, 2, false><<<dim3(39, 16, 1), 256, SM_BB>>>(
        X2, W3, 2048, 16, 16, 32, 2048, 1, NOUT,
        nullptr, nullptr, c1b, cls1T, NOUT);
    // 12) res2 -> aug
    split_aug<<<dim3(512, 8, 8), 256>>>(res2, Xr2, 256, 16384);
    // 13) c1a GEMM: K' = 4608 (72 chunks) -> c1aT fp32
    gemm_mma<128, 48, 1, true><<<dim3(1, 1024, 1), 256, SM_C4>>>(
        Xr2, W4, 512, 128, 128, 72, 4608, 2, 48,
        bn3s, bn3h, nullptr, c1aT, 48);
    // 14) fused tail
    fused_final<<<dim3(256, 8), 256>>>(cls1T, c1aT, bw2, bb2, cats, cath, out);
}

// round 11
// speedup vs baseline: 2.4656x; 1.3848x over previous
#include <cuda_runtime.h>
#include <cuda_fp16.h>
#include <cstdint>

typedef __half h16;
#define NOUT 4928

// ---------------- scratch (device globals; sizes in elements) ----------------
__device__ __align__(16) h16 g_Xs5[(size_t)2048 * 2048];     // res5 fp16 [pos][2048]
__device__ __align__(16) h16 g_W1 [(size_t)512 * 18432];     // conv1 W fp16 [oc][9*2048]
__device__ __align__(16) h16 g_X1 [(size_t)2048 * 512];      // x1 fp16 [pos][512]
__device__ __align__(16) h16 g_W2 [(size_t)1024 * 4608];     // conv2 W fp16 (moving 512 cin)
__device__ __align__(16) h16 g_X2 [(size_t)2048 * 2048];     // x2 aug [pos][h(1024)|l(1024)]
__device__ __align__(16) h16 g_W3 [(size_t)4992 * 2048];     // cls1 W aug (oc padded, dup)
__device__ __align__(16) h16 g_Xr2[(size_t)131072 * 256];    // res2 fp16
__device__ __align__(16) h16 g_W4 [(size_t)64 * 2304];       // c1a W fp16 (oc padded)
__device__ float g_gp [8 * 512];
__device__ float g_C9 [(size_t)8 * 1024 * 9];
__device__ float g_cls1T[(size_t)2048 * NOUT];               // also split-K partial buffer
__device__ float g_c1aT [(size_t)131072 * 48];

// ---------------- helpers ----------------
__device__ __forceinline__ void split2h(float v, h16& h, h16& l) {
    h = __float2half_rn(v);
    l = __float2half_rn(v - __half2float(h));
}
__device__ __forceinline__ unsigned s2u(const void* p) {
    return (unsigned)__cvta_generic_to_shared(p);
}
__device__ __forceinline__ void cpa16(unsigned d, const void* s, unsigned sz) {
    asm volatile("cp.async.ca.shared.global [%0], [%1], 16, %2;" :: "r"(d), "l"(s), "r"(sz));
}
__device__ __forceinline__ void cpa_commit() {
    asm volatile("cp.async.commit_group;" ::: "memory");
}
template<int N> __device__ __forceinline__ void cpa_wait() {
    asm volatile("cp.async.wait_group %0;" :: "n"(N) : "memory");
}
__device__ __forceinline__ void ldm4(unsigned* r, unsigned a) {
    asm volatile("ldmatrix.sync.aligned.m8n8.x4.shared.b16 {%0,%1,%2,%3}, [%4];"
        : "=r"(r[0]), "=r"(r[1]), "=r"(r[2]), "=r"(r[3]) : "r"(a));
}
__device__ __forceinline__ void mma16816(float* d, const unsigned* a, const unsigned* b) {
    asm volatile("mma.sync.aligned.m16n8k16.row.col.f32.f16.f16.f32 "
        "{%0,%1,%2,%3}, {%4,%5,%6,%7}, {%8,%9}, {%0,%1,%2,%3};"
        : "+f"(d[0]), "+f"(d[1]), "+f"(d[2]), "+f"(d[3])
        : "r"(a[0]), "r"(a[1]), "r"(a[2]), "r"(a[3]), "r"(b[0]), "r"(b[1]));
}

// =====================================================================
// HMMA fp16 GEMM: BK=64, 3-stage cp.async pipeline, 2 CTAs/SM.
// 8 warps as (8/WS) m x WS n.  SMEM row stride 144B (conflict-free).
// epi: 1 = +bias -> fp32 (guarded); 2 = BN+ReLU -> fp32 (guarded);
//      4 = raw fp32 split-K partial at [blockIdx.z][M][ofc]
// =====================================================================
template<int BM, int BN, int WS, bool CONV3>
__global__ __launch_bounds__(256, 2) void gemm_mma(
    const h16* __restrict__ A, const h16* __restrict__ B,
    int C3, int imh, int imw, int nk, int Kb,
    int epi, int nvalid,
    const float* __restrict__ scale, const float* __restrict__ shift,
    const float* __restrict__ bias,
    float* __restrict__ Of, int ofc)
{
    constexpr int WM = BM / (8 / WS), WN = BN / WS;
    constexpr int MT = WM / 16;
    constexpr int NT = WN / 8;
    constexpr int NF = WN / 16;
    constexpr int AJ = BM / 32;
    constexpr int BJ = (BN * 8 + 255) / 256;
    constexpr int ABYTES = BM * 144, STG = (BM + BN) * 144;

    extern __shared__ __align__(16) char sm[];
    const int tid = threadIdx.x;
    const int nb = blockIdx.x, mtile = blockIdx.y;
    const int kzoff = blockIdx.z * nk;
    const int warp = tid >> 5, lane = tid & 31;
    const int m0 = (warp / WS) * WM, n0 = (warp % WS) * WN;
    const unsigned sbase = s2u(sm);
    const int imgpix = imh * imw;
    const int vec = tid & 7;

    int arow[AJ], ay[AJ], ax[AJ], apb[AJ];
#pragma unroll
    for (int j = 0; j < AJ; j++) {
        arow[j] = (tid >> 3) + j * 32;
        int g = mtile * BM + arow[j];
        if (CONV3) {
            int bb = g / imgpix, lp = g - bb * imgpix;
            ay[j] = lp / imw; ax[j] = lp - ay[j] * imw; apb[j] = bb * imgpix;
        } else { ay[j] = 0; ax[j] = 0; apb[j] = g; }
    }

    auto load_chunk = [&](int kc, int st) {
        unsigned Ab = sbase + st * STG;
        unsigned Bb = Ab + ABYTES;
        int k0 = (kzoff + kc) * 64;
        int dy = 0, dx = 0, cb = k0;
        if (CONV3) {
            int rk = k0 / C3; cb = k0 - rk * C3;
            int r3 = rk / 3; dy = r3 - 1; dx = rk - r3 * 3 - 1;
        }
#pragma unroll
        for (int j = 0; j < AJ; j++) {
            const h16* src;
            unsigned sz = 16;
            if (CONV3) {
                int y2 = ay[j] + dy, x2 = ax[j] + dx;
                bool v = ((unsigned)y2 < (unsigned)imh) && ((unsigned)x2 < (unsigned)imw);
                src = A + (size_t)(apb[j] + y2 * imw + x2) * C3 + cb + vec * 8;
                if (!v) { src = A; sz = 0; }
            } else {
                src = A + (size_t)apb[j] * C3 + k0 + vec * 8;
            }
            cpa16(Ab + arow[j] * 144 + vec * 16, src, sz);
        }
#pragma unroll
        for (int j = 0; j < BJ; j++) {
            int item = tid + 256 * j;
            int row = item >> 3;
            if ((BN * 8 % 256 == 0) || item < BN * 8)
                cpa16(Bb + row * 144 + (item & 7) * 16,
                      B + (size_t)(nb * BN + row) * Kb + k0 + (item & 7) * 8, 16);
        }
    };

    float acc[MT][NT][4];
#pragma unroll
    for (int a = 0; a < MT; a++)
#pragma unroll
        for (int b2 = 0; b2 < NT; b2++)
#pragma unroll
            for (int c = 0; c < 4; c++) acc[a][b2][c] = 0.f;

    auto compute = [&](int st) {
        unsigned Ab = sbase + st * STG;
        unsigned Bb = Ab + ABYTES;
#pragma unroll
        for (int step = 0; step < 4; step++) {
            unsigned af[MT][4], bfr[NF][4];
            {
                int ch = step * 2 + (lane >> 4);
#pragma unroll
                for (int i = 0; i < MT; i++)
                    ldm4(af[i], Ab + (m0 + 16 * i + (lane & 15)) * 144 + ch * 16);
            }
            {
                int rr = (lane & 7) + ((lane >> 4) << 3);
                int ch = step * 2 + ((lane >> 3) & 1);
#pragma unroll
                for (int i = 0; i < NF; i++)
                    ldm4(bfr[i], Bb + (n0 + 16 * i + rr) * 144 + ch * 16);
            }
#pragma unroll
            for (int mt = 0; mt < MT; mt++)
#pragma unroll
                for (int nt = 0; nt < NT; nt++)
                    mma16816(acc[mt][nt], af[mt], &bfr[nt >> 1][(nt & 1) * 2]);
        }
    };

    load_chunk(0, 0);
    cpa_commit();
    if (nk > 1) load_chunk(1, 1);
    cpa_commit();
    int st2 = 2;
    for (int kc = 0; kc < nk; kc++) {
        cpa_wait<1>();
        __syncthreads();
        if (kc + 2 < nk) {
            load_chunk(kc + 2, st2);
            if (++st2 == 3) st2 = 0;
        }
        cpa_commit();
        compute(kc % 3);
    }

    // ---- epilogue ----
    float* dstz = Of;
    if (epi == 4)
        dstz = Of + (size_t)blockIdx.z * ((size_t)gridDim.y * BM) * ofc;
#pragma unroll
    for (int mt = 0; mt < MT; mt++)
#pragma unroll
        for (int nt = 0; nt < NT; nt++) {
            float* d = acc[mt][nt];
            int row = mtile * BM + m0 + mt * 16 + (lane >> 2);
            int col = nb * BN + n0 + nt * 8 + (lane & 3) * 2;
#pragma unroll
            for (int h = 0; h < 2; h++) {
                int r = row + h * 8;
                float v0 = d[h * 2 + 0], v1 = d[h * 2 + 1];
                if (epi == 4) {
                    *(float2*)(dstz + (size_t)r * ofc + col) = make_float2(v0, v1);
                } else if (epi == 1) {
                    if (col < nvalid) {
                        float2 o = make_float2(v0 + bias[col], v1 + bias[col + 1]);
                        *(float2*)(Of + (size_t)r * ofc + col) = o;
                    }
                } else {
                    if (col < nvalid) {
                        float2 o;
                        o.x = fmaxf(fmaf(v0, scale[col], shift[col]), 0.f);
                        o.y = fmaxf(fmaf(v1, scale[col + 1], shift[col + 1]), 0.f);
                        *(float2*)(Of + (size_t)r * ofc + col) = o;
                    }
                }
            }
        }
}

// ---------------- reduce split-K partials + (opt C9) + BN/ReLU -> fp16 ----------------
// aug = 1: single fp16 [pos][C];  aug = 2: hi/lo [pos][h(C)|l(C)]
__global__ __launch_bounds__(256) void reduce_aug(
    const float* __restrict__ P, int ns, int M, int C, int aug,
    const float* __restrict__ corr,
    const float* __restrict__ scale, const float* __restrict__ shift,
    h16* __restrict__ out)
{
    int idx = blockIdx.x * 256 + threadIdx.x;
    int r = idx / C, col = idx - r * C;
    if (r >= M) return;
    float v = 0.f;
    for (int s = 0; s < ns; s++) v += P[((size_t)s * M + r) * C + col];
    if (corr) {
        int lp = r & 255, y = lp >> 4, xp = lp & 15;
        int cls = ((y == 0) ? 0 : ((y == 15) ? 6 : 3))
                + ((xp == 0) ? 0 : ((xp == 15) ? 2 : 1));
        v += corr[((size_t)(r >> 8) * 1024 + col) * 9 + cls];
    }
    v = fmaxf(fmaf(v, scale[col], shift[col]), 0.f);
    if (aug == 2) {
        h16 h, l; split2h(v, h, l);
        size_t base = (size_t)r * 2 * C + col;
        out[base] = h; out[base + C] = l;
    } else {
        out[(size_t)r * C + col] = __float2half_rn(v);
    }
}

// ---------------- prep: NCHW fp32 -> [pos][C] fp16 ----------------
__global__ __launch_bounds__(256) void split_aug(
    const float* __restrict__ in, h16* __restrict__ out, int C, int HW)
{
    __shared__ float t[32][33];
    const int b = blockIdx.z, c0 = blockIdx.y * 32, p0 = blockIdx.x * 32;
    const int tx = threadIdx.x & 31, ty = threadIdx.x >> 5;
#pragma unroll
    for (int r = 0; r < 4; r++)
        t[ty + 8 * r][tx] = in[((size_t)b * C + c0 + ty + 8 * r) * HW + p0 + tx];
    __syncthreads();
#pragma unroll
    for (int r = 0; r < 4; r++) {
        int p = p0 + ty + 8 * r;
        out[((size_t)b * HW + p) * C + c0 + tx] = __float2half_rn(t[tx][ty + 8 * r]);
    }
}

// ---------------- prep: conv1 weight OIHW -> [oc][tap*C + c] fp16 ----------------
__global__ __launch_bounds__(256) void wsplit_conv_aug(
    const float* __restrict__ w, h16* __restrict__ out, int C, int OC)
{
    int idx = blockIdx.x * 256 + threadIdx.x;
    int oc = idx / (9 * C); int rem = idx - oc * 9 * C;
    int tap = rem / C; int c = rem - tap * C;
    float v = (oc < OC) ? w[((size_t)oc * C + c) * 9 + tap] : 0.f;
    out[(size_t)oc * 9 * C + (size_t)tap * C + c] = __float2half_rn(v);
}

// ---------------- prep: conv2 weight, moving cin 0..511 only ----------------
__global__ __launch_bounds__(256) void wsplit_conv2(
    const float* __restrict__ w, h16* __restrict__ out)
{
    int idx = blockIdx.x * 256 + threadIdx.x;   // 1024 * 9 * 512
    int oc = idx / (9 * 512); int rem = idx - oc * 9 * 512;
    int tap = rem / 512; int c = rem - tap * 512;
    out[(size_t)oc * 4608 + (size_t)tap * 512 + c] =
        __float2half_rn(w[((size_t)oc * 1024 + c) * 9 + tap]);
}

// ---------------- merged small prep: c1a W fp16 + cls1 W aug(dup) ----------------
__global__ __launch_bounds__(256) void wsplit_small(
    const float* __restrict__ aw, const float* __restrict__ c1w,
    h16* __restrict__ W4, h16* __restrict__ W3)
{
    const int N4 = 64 * 9 * 256;
    int idx = blockIdx.x * 256 + threadIdx.x;
    if (idx < N4) {
        int oc = idx / (9 * 256); int rem = idx - oc * 9 * 256;
        int tap = rem / 256; int c = rem - tap * 256;
        float v = (oc < 48) ? aw[((size_t)oc * 256 + c) * 9 + tap] : 0.f;
        W4[(size_t)oc * 2304 + (size_t)tap * 256 + c] = __float2half_rn(v);
    } else {
        int i2 = idx - N4;
        if (i2 < 4992 * 1024) {
            int oc = i2 >> 10, c = i2 & 1023;
            float v = (oc < NOUT) ? c1w[(size_t)oc * 1024 + c] : 0.f;
            h16 h = __float2half_rn(v);
            size_t base = (size_t)oc * 2048;
            W3[base + c] = h; W3[base + 1024 + c] = h;
        }
    }
}

// ---------------- gp reduce over X1 fp16, deterministic ----------------
__global__ __launch_bounds__(512) void gp_reduce(
    const h16* __restrict__ X1, float* __restrict__ gp)
{
    const int b = blockIdx.x, c = threadIdx.x;    // c in [0,512)
    float s = 0.f;
    for (int p = 0; p < 256; p++)
        s += __half2float(X1[((size_t)(b * 256 + p)) * 512 + c]);
    gp[b * 512 + c] = s * (1.f / 256.f);
}

// ---------------- C9: per-(b, oc, boundary-class) gp correction ----------------
__global__ __launch_bounds__(128) void c9_kernel(
    const float* __restrict__ w, const float* __restrict__ gp, float* __restrict__ C9)
{
    __shared__ float sgp[512];
    __shared__ float sT[16][9];
    const int b = blockIdx.y, oc0 = blockIdx.x * 16, tid = threadIdx.x;
    for (int i = tid; i < 512; i += 128) sgp[i] = gp[b * 512 + i];
    __syncthreads();

    const int oc = oc0 + (tid >> 3), ln = tid & 7;
    float t[9];
#pragma unroll
    for (int k = 0; k < 9; k++) t[k] = 0.f;
    for (int c = ln * 64; c < ln * 64 + 64; c++) {
        float g = sgp[c];
        const float* wp = w + ((size_t)oc * 1024 + 512 + c) * 9;
#pragma unroll
        for (int k = 0; k < 9; k++) t[k] = fmaf(wp[k], g, t[k]);
    }
#pragma unroll
    for (int o = 4; o; o >>= 1)
#pragma unroll
        for (int k = 0; k < 9; k++) t[k] += __shfl_down_sync(0xffffffffu, t[k], o, 8);
    if (ln == 0)
#pragma unroll
        for (int k = 0; k < 9; k++) sT[tid >> 3][k] = t[k];
    __syncthreads();

    for (int i = tid; i < 144; i += 128) {
        int o = i / 9, cls = i - (i / 9) * 9;
        int fy = cls / 3, fx = cls - fy * 3;
        float s = 0.f;
#pragma unroll
        for (int ky = 0; ky < 3; ky++) {
            if ((fy == 0 && ky == 0) || (fy == 2 && ky == 2)) continue;
#pragma unroll
            for (int kx = 0; kx < 3; kx++) {
                if ((fx == 0 && kx == 0) || (fx == 2 && kx == 2)) continue;
                s += sT[o][ky * 3 + kx];
            }
        }
        C9[((size_t)b * 1024 + oc0 + o) * 9 + cls] = s;
    }
}

// ---------------- fused: c1b + coord + cat-BN + 3-layer dynamic MLP ----------------
__global__ __launch_bounds__(256) void fused_final(
    const float* __restrict__ cls1T, const float* __restrict__ c1aT,
    const float* __restrict__ c1b_w, const float* __restrict__ c1b_b,
    const float* __restrict__ cat_scale, const float* __restrict__ cat_shift,
    float* __restrict__ out)
{
    const int b = blockIdx.y, lpos = blockIdx.x;
    const int ly = lpos >> 4, lx = lpos & 15;
    const int tid = threadIdx.x;
    const int px = tid & 63, q = tid >> 6;
    const int py = px >> 3, pxx = px & 7;

    __shared__ float sP[NOUT];
    __shared__ float sA[48 * 64];
    __shared__ float sI[18 * 64];
    __shared__ float sH0[16 * 64];
    __shared__ float sH1[16 * 64];
    __shared__ float sWb[768 + 16];

    const float* pp = cls1T + (size_t)(b * 256 + lpos) * NOUT;
    for (int i = tid; i < NOUT; i += 256) sP[i] = pp[i];
    for (int i = tid; i < 48 * 64; i += 256) {
        int p = i / 48, ch = i - p * 48;
        int yy = ly * 8 + (p >> 3), xx = lx * 8 + (p & 7);
        sA[ch * 64 + p] = c1aT[((size_t)b * 16384 + yy * 128 + xx) * 48 + ch];
    }
    for (int i = tid; i < 768; i += 256) sWb[i] = c1b_w[i];
    if (tid < 16) sWb[768 + tid] = c1b_b[tid];
    __syncthreads();

#pragma unroll
    for (int jj = 0; jj < 4; jj++) {
        int j = q * 4 + jj;
        float s = sWb[768 + j];
#pragma unroll
        for (int c = 0; c < 48; c++)
            s = fmaf(sA[c * 64 + px], sWb[j * 48 + c], s);
        sI[(2 + j) * 64 + px] = fmaf(s, cat_scale[2 + j], cat_shift[2 + j]);
    }
    if (q == 0) {
        sI[px]      = fmaf((float)pxx * 0.125f, cat_scale[0], cat_shift[0]);
        sI[64 + px] = fmaf((float)py  * 0.125f, cat_scale[1], cat_shift[1]);
    }
    __syncthreads();

#pragma unroll
    for (int jj = 0; jj < 4; jj++) {
        int o = q * 4 + jj;
        float s = sP[288 + o];
#pragma unroll
        for (int c = 0; c < 18; c++)
            s = fmaf(sP[o * 18 + c], sI[c * 64 + px], s);
        sH0[o * 64 + px] = fmaxf(s, 0.f);
    }
    __syncthreads();

#pragma unroll
    for (int jj = 0; jj < 4; jj++) {
        int o = q * 4 + jj;
        float s = sP[560 + o];
#pragma unroll
        for (int c = 0; c < 16; c++)
            s = fmaf(sP[304 + o * 16 + c], sH0[c * 64 + px], s);
        sH1[o * 64 + px] = fmaxf(s, 0.f);
    }
    __syncthreads();

    float hr[16];
#pragma unroll
    for (int c = 0; c < 16; c++) hr[c] = sH1[c * 64 + px];
    const int y = ly * 8 + py, x = lx * 8 + pxx;
    float* ob = out + (((size_t)b * 256) << 14) + (y << 7) + x;
#pragma unroll 4
    for (int oo = 0; oo < 64; oo++) {
        int o = q * 64 + oo;
        float s = sP[4672 + o];
#pragma unroll
        for (int c = 0; c < 16; c++)
            s = fmaf(sP[576 + o * 16 + c], hr[c], s);
        ob[(size_t)o << 14] = s;
    }
}

// ---------------- host launcher ----------------
extern "C" void kernel_launch(void* const* d_in, const int* in_sizes, int n_in,
                              void* d_out, int out_size)
{
    const float* res5 = (const float*)d_in[0];
    const float* res2 = (const float*)d_in[1];
    const float* bw   = (const float*)d_in[2];
    const float* bn1s = (const float*)d_in[3];
    const float* bn1h = (const float*)d_in[4];
    const float* c0w  = (const float*)d_in[5];
    const float* bn2s = (const float*)d_in[6];
    const float* bn2h = (const float*)d_in[7];
    const float* c1w  = (const float*)d_in[8];
    const float* c1b  = (const float*)d_in[9];
    const float* aw   = (const float*)d_in[10];
    const float* bn3s = (const float*)d_in[11];
    const float* bn3h = (const float*)d_in[12];
    const float* bw2  = (const float*)d_in[13];
    const float* bb2  = (const float*)d_in[14];
    const float* cats = (const float*)d_in[15];
    const float* cath = (const float*)d_in[16];
    float* out = (float*)d_out;

    h16 *Xs5, *W1, *X1, *W2, *X2, *W3, *Xr2, *W4;
    float *gp, *C9, *cls1T, *c1aT;
    cudaGetSymbolAddress((void**)&Xs5, g_Xs5);
    cudaGetSymbolAddress((void**)&W1,  g_W1);
    cudaGetSymbolAddress((void**)&X1,  g_X1);
    cudaGetSymbolAddress((void**)&W2,  g_W2);
    cudaGetSymbolAddress((void**)&X2,  g_X2);
    cudaGetSymbolAddress((void**)&W3,  g_W3);
    cudaGetSymbolAddress((void**)&Xr2, g_Xr2);
    cudaGetSymbolAddress((void**)&W4,  g_W4);
    cudaGetSymbolAddress((void**)&gp,  g_gp);
    cudaGetSymbolAddress((void**)&C9,  g_C9);
    cudaGetSymbolAddress((void**)&cls1T, g_cls1T);
    cudaGetSymbolAddress((void**)&c1aT,  g_c1aT);

    const int SM_C1 = (128 + 64) * 144 * 3;    // 82944
    const int SM_BB = (128 + 128) * 144 * 3;   // 110592
    const int SM_C4 = (128 + 48) * 144 * 3;    // 76032
    cudaFuncSetAttribute(gemm_mma<128, 64, 2, true>,   cudaFuncAttributeMaxDynamicSharedMemorySize, SM_C1);
    cudaFuncSetAttribute(gemm_mma<128, 128, 2, true>,  cudaFuncAttributeMaxDynamicSharedMemorySize, SM_BB);
    cudaFuncSetAttribute(gemm_mma<128, 128, 2, false>, cudaFuncAttributeMaxDynamicSharedMemorySize, SM_BB);
    cudaFuncSetAttribute(gemm_mma<128, 48, 1, true>,   cudaFuncAttributeMaxDynamicSharedMemorySize, SM_C4);

    // 1) res5 -> fp16 [pos][2048]
    split_aug<<<dim3(8, 64, 8), 256>>>(res5, Xs5, 2048, 256);
    // 2) conv1 weights -> fp16 [oc][18432]
    wsplit_conv_aug<<<(512 * 9 * 2048) / 256, 256>>>(bw, W1, 2048, 512);
    // 3) conv1 GEMM: K = 18432, split-K x3 (96 chunks each) -> partials
    gemm_mma<128, 64, 2, true><<<dim3(8, 16, 3), 256, SM_C1>>>(
        Xs5, W1, 2048, 16, 16, 96, 18432, 4, 512,
        nullptr, nullptr, nullptr, cls1T, 512);
    // 4) reduce -> X1 fp16 (single)
    reduce_aug<<<(2048 * 512) / 256, 256>>>(cls1T, 3, 2048, 512, 1, nullptr, bn1s, bn1h, X1);
    // 5) global pool
    gp_reduce<<<8, 512>>>(X1, gp);
    // 6) C9 correction table
    c9_kernel<<<dim3(64, 8), 128>>>(c0w, gp, C9);
    // 7) conv2 weights -> fp16 [oc][4608]
    wsplit_conv2<<<(1024 * 9 * 512) / 256, 256>>>(c0w, W2);
    // 8) conv2 GEMM: K = 4608, split-K x2 (36 chunks each)
    gemm_mma<128, 128, 2, true><<<dim3(8, 16, 2), 256, SM_BB>>>(
        X1, W2, 512, 16, 16, 36, 4608, 4, 1024,
        nullptr, nullptr, nullptr, cls1T, 1024);
    // 9) reduce (+C9) -> X2 aug hi/lo (2-term for cls1 precision)
    reduce_aug<<<(2048 * 1024) / 256, 256>>>(cls1T, 2, 2048, 1024, 2, C9, bn2s, bn2h, X2);
    // 10) small weights: c1a fp16 + cls1 aug
    wsplit_small<<<(64 * 9 * 256 + 4992 * 1024 + 255) / 256, 256>>>(aw, c1w, W4, W3);
    // 11) cls1 GEMM: K' = 2048 (32 chunks) -> cls1T fp32
    gemm_mma<128, 128, 2, false><<<dim3(39, 16, 1), 256, SM_BB>>>(
        X2, W3, 2048, 16, 16, 32, 2048, 1, NOUT,
        nullptr, nullptr, c1b, cls1T, NOUT);
    // 12) res2 -> fp16 [pos][256]
    split_aug<<<dim3(512, 8, 8), 256>>>(res2, Xr2, 256, 16384);
    // 13) c1a GEMM: K = 2304 (36 chunks) -> c1aT fp32
    gemm_mma<128, 48, 1, true><<<dim3(1, 1024, 1), 256, SM_C4>>>(
        Xr2, W4, 256, 128, 128, 36, 2304, 2, 48,
        bn3s, bn3h, nullptr, c1aT, 48);
    // 14) fused tail
    fused_final<<<dim3(256, 8), 256>>>(cls1T, c1aT, bw2, bb2, cats, cath, out);
}

// round 12
// speedup vs baseline: 2.6319x; 1.0674x over previous
#include <cuda_runtime.h>
#include <cuda_fp16.h>
#include <cstdint>

typedef __half h16;
#define NOUT 4928

// ---------------- scratch (device globals; sizes in elements) ----------------
__device__ __align__(16) h16 g_Xs5[(size_t)2048 * 2048];     // res5 fp16 [pos][2048]
__device__ __align__(16) h16 g_W1 [(size_t)512 * 18432];     // conv1 W fp16
__device__ __align__(16) h16 g_X1 [(size_t)2048 * 512];      // x1 fp16
__device__ __align__(16) h16 g_W2 [(size_t)1024 * 4608];     // conv2 W fp16 (moving 512 cin)
__device__ __align__(16) h16 g_X2 [(size_t)2048 * 1024];     // x2 fp16 (single)
__device__ __align__(16) h16 g_W3 [(size_t)4992 * 1024];     // cls1 W fp16 (oc padded)
__device__ __align__(16) h16 g_Xr2[(size_t)131072 * 256];    // res2 fp16
__device__ __align__(16) h16 g_W4 [(size_t)64 * 2304];       // c1a W fp16
__device__ float g_gp [8 * 512];
__device__ float g_C9 [(size_t)8 * 1024 * 9];
__device__ float g_cls1T[(size_t)2048 * NOUT];               // also split-K partial buffer
__device__ float g_c1aT [(size_t)131072 * 48];

// ---------------- helpers ----------------
__device__ __forceinline__ unsigned s2u(const void* p) {
    return (unsigned)__cvta_generic_to_shared(p);
}
__device__ __forceinline__ void cpa16(unsigned d, const void* s, unsigned sz) {
    asm volatile("cp.async.ca.shared.global [%0], [%1], 16, %2;" :: "r"(d), "l"(s), "r"(sz));
}
__device__ __forceinline__ void cpa_commit() {
    asm volatile("cp.async.commit_group;" ::: "memory");
}
template<int N> __device__ __forceinline__ void cpa_wait() {
    asm volatile("cp.async.wait_group %0;" :: "n"(N) : "memory");
}
__device__ __forceinline__ void ldm4(unsigned* r, unsigned a) {
    asm volatile("ldmatrix.sync.aligned.m8n8.x4.shared.b16 {%0,%1,%2,%3}, [%4];"
        : "=r"(r[0]), "=r"(r[1]), "=r"(r[2]), "=r"(r[3]) : "r"(a));
}
__device__ __forceinline__ void mma16816(float* d, const unsigned* a, const unsigned* b) {
    asm volatile("mma.sync.aligned.m16n8k16.row.col.f32.f16.f16.f32 "
        "{%0,%1,%2,%3}, {%4,%5,%6,%7}, {%8,%9}, {%0,%1,%2,%3};"
        : "+f"(d[0]), "+f"(d[1]), "+f"(d[2]), "+f"(d[3])
        : "r"(a[0]), "r"(a[1]), "r"(a[2]), "r"(a[3]), "r"(b[0]), "r"(b[1]));
}

// =====================================================================
// HMMA fp16 GEMM: BK=64, 3-stage cp.async pipeline, 2 CTAs/SM.
// epi: 1 = +bias -> fp32 (guarded); 2 = BN+ReLU -> fp32 (guarded);
//      4 = raw fp32 split-K partial at [blockIdx.z][M][ofc]
// =====================================================================
template<int BM, int BN, int WS, bool CONV3>
__global__ __launch_bounds__(256, 2) void gemm_mma(
    const h16* __restrict__ A, const h16* __restrict__ B,
    int C3, int imh, int imw, int nk, int Kb,
    int epi, int nvalid,
    const float* __restrict__ scale, const float* __restrict__ shift,
    const float* __restrict__ bias,
    float* __restrict__ Of, int ofc)
{
    constexpr int WM = BM / (8 / WS), WN = BN / WS;
    constexpr int MT = WM / 16;
    constexpr int NT = WN / 8;
    constexpr int NF = WN / 16;
    constexpr int AJ = BM / 32;
    constexpr int BJ = (BN * 8 + 255) / 256;
    constexpr int ABYTES = BM * 144, STG = (BM + BN) * 144;

    extern __shared__ __align__(16) char sm[];
    const int tid = threadIdx.x;
    const int nb = blockIdx.x, mtile = blockIdx.y;
    const int kzoff = blockIdx.z * nk;
    const int warp = tid >> 5, lane = tid & 31;
    const int m0 = (warp / WS) * WM, n0 = (warp % WS) * WN;
    const unsigned sbase = s2u(sm);
    const int imgpix = imh * imw;
    const int vec = tid & 7;

    int arow[AJ], ay[AJ], ax[AJ], apb[AJ];
#pragma unroll
    for (int j = 0; j < AJ; j++) {
        arow[j] = (tid >> 3) + j * 32;
        int g = mtile * BM + arow[j];
        if (CONV3) {
            int bb = g / imgpix, lp = g - bb * imgpix;
            ay[j] = lp / imw; ax[j] = lp - ay[j] * imw; apb[j] = bb * imgpix;
        } else { ay[j] = 0; ax[j] = 0; apb[j] = g; }
    }

    auto load_chunk = [&](int kc, int st) {
        unsigned Ab = sbase + st * STG;
        unsigned Bb = Ab + ABYTES;
        int k0 = (kzoff + kc) * 64;
        int dy = 0, dx = 0, cb = k0;
        if (CONV3) {
            int rk = k0 / C3; cb = k0 - rk * C3;
            int r3 = rk / 3; dy = r3 - 1; dx = rk - r3 * 3 - 1;
        }
#pragma unroll
        for (int j = 0; j < AJ; j++) {
            const h16* src;
            unsigned sz = 16;
            if (CONV3) {
                int y2 = ay[j] + dy, x2 = ax[j] + dx;
                bool v = ((unsigned)y2 < (unsigned)imh) && ((unsigned)x2 < (unsigned)imw);
                src = A + (size_t)(apb[j] + y2 * imw + x2) * C3 + cb + vec * 8;
                if (!v) { src = A; sz = 0; }
            } else {
                src = A + (size_t)apb[j] * C3 + k0 + vec * 8;
            }
            cpa16(Ab + arow[j] * 144 + vec * 16, src, sz);
        }
#pragma unroll
        for (int j = 0; j < BJ; j++) {
            int item = tid + 256 * j;
            int row = item >> 3;
            if ((BN * 8 % 256 == 0) || item < BN * 8)
                cpa16(Bb + row * 144 + (item & 7) * 16,
                      B + (size_t)(nb * BN + row) * Kb + k0 + (item & 7) * 8, 16);
        }
    };

    float acc[MT][NT][4];
#pragma unroll
    for (int a = 0; a < MT; a++)
#pragma unroll
        for (int b2 = 0; b2 < NT; b2++)
#pragma unroll
            for (int c = 0; c < 4; c++) acc[a][b2][c] = 0.f;

    auto compute = [&](int st) {
        unsigned Ab = sbase + st * STG;
        unsigned Bb = Ab + ABYTES;
#pragma unroll
        for (int step = 0; step < 4; step++) {
            unsigned af[MT][4], bfr[NF][4];
            {
                int ch = step * 2 + (lane >> 4);
#pragma unroll
                for (int i = 0; i < MT; i++)
                    ldm4(af[i], Ab + (m0 + 16 * i + (lane & 15)) * 144 + ch * 16);
            }
            {
                int rr = (lane & 7) + ((lane >> 4) << 3);
                int ch = step * 2 + ((lane >> 3) & 1);
#pragma unroll
                for (int i = 0; i < NF; i++)
                    ldm4(bfr[i], Bb + (n0 + 16 * i + rr) * 144 + ch * 16);
            }
#pragma unroll
            for (int mt = 0; mt < MT; mt++)
#pragma unroll
                for (int nt = 0; nt < NT; nt++)
                    mma16816(acc[mt][nt], af[mt], &bfr[nt >> 1][(nt & 1) * 2]);
        }
    };

    load_chunk(0, 0);
    cpa_commit();
    if (nk > 1) load_chunk(1, 1);
    cpa_commit();
    int st2 = 2;
    for (int kc = 0; kc < nk; kc++) {
        cpa_wait<1>();
        __syncthreads();
        if (kc + 2 < nk) {
            load_chunk(kc + 2, st2);
            if (++st2 == 3) st2 = 0;
        }
        cpa_commit();
        compute(kc % 3);
    }

    // ---- epilogue ----
    float* dstz = Of;
    if (epi == 4)
        dstz = Of + (size_t)blockIdx.z * ((size_t)gridDim.y * BM) * ofc;
#pragma unroll
    for (int mt = 0; mt < MT; mt++)
#pragma unroll
        for (int nt = 0; nt < NT; nt++) {
            float* d = acc[mt][nt];
            int row = mtile * BM + m0 + mt * 16 + (lane >> 2);
            int col = nb * BN + n0 + nt * 8 + (lane & 3) * 2;
#pragma unroll
            for (int h = 0; h < 2; h++) {
                int r = row + h * 8;
                float v0 = d[h * 2 + 0], v1 = d[h * 2 + 1];
                if (epi == 4) {
                    *(float2*)(dstz + (size_t)r * ofc + col) = make_float2(v0, v1);
                } else if (epi == 1) {
                    if (col < nvalid) {
                        float2 o = make_float2(v0 + bias[col], v1 + bias[col + 1]);
                        *(float2*)(Of + (size_t)r * ofc + col) = o;
                    }
                } else {
                    if (col < nvalid) {
                        float2 o;
                        o.x = fmaxf(fmaf(v0, scale[col], shift[col]), 0.f);
                        o.y = fmaxf(fmaf(v1, scale[col + 1], shift[col + 1]), 0.f);
                        *(float2*)(Of + (size_t)r * ofc + col) = o;
                    }
                }
            }
        }
}

// ---------------- reduce split-K partials + (opt C9) + BN/ReLU -> fp16 ----------------
// vectorized x4; C multiple of 4
__global__ __launch_bounds__(256) void reduce_aug(
    const float* __restrict__ P, int ns, int M, int C,
    const float* __restrict__ corr,
    const float* __restrict__ scale, const float* __restrict__ shift,
    h16* __restrict__ out)
{
    int idx = (blockIdx.x * 256 + threadIdx.x) * 4;
    int r = idx / C, col = idx - r * C;
    if (r >= M) return;
    float4 v = *(const float4*)(P + (size_t)r * C + col);
    for (int s = 1; s < ns; s++) {
        float4 p = *(const float4*)(P + ((size_t)s * M + r) * C + col);
        v.x += p.x; v.y += p.y; v.z += p.z; v.w += p.w;
    }
    if (corr) {
        int lp = r & 255, y = lp >> 4, xp = lp & 15;
        int cls = ((y == 0) ? 0 : ((y == 15) ? 6 : 3))
                + ((xp == 0) ? 0 : ((xp == 15) ? 2 : 1));
        const float* cp = corr + (size_t)(r >> 8) * 1024 * 9 + (size_t)col * 9 + cls;
        v.x += cp[0]; v.y += cp[9]; v.z += cp[18]; v.w += cp[27];
    }
    float4 sc = *(const float4*)(scale + col);
    float4 sh = *(const float4*)(shift + col);
    v.x = fmaxf(fmaf(v.x, sc.x, sh.x), 0.f);
    v.y = fmaxf(fmaf(v.y, sc.y, sh.y), 0.f);
    v.z = fmaxf(fmaf(v.z, sc.z, sh.z), 0.f);
    v.w = fmaxf(fmaf(v.w, sc.w, sh.w), 0.f);
    ushort4 u;
    u.x = __half_as_ushort(__float2half_rn(v.x));
    u.y = __half_as_ushort(__float2half_rn(v.y));
    u.z = __half_as_ushort(__float2half_rn(v.z));
    u.w = __half_as_ushort(__float2half_rn(v.w));
    *(ushort4*)(out + (size_t)r * C + col) = u;
}

// ---------------- prep: NCHW fp32 -> [pos][C] fp16 ----------------
__global__ __launch_bounds__(256) void split_aug(
    const float* __restrict__ in, h16* __restrict__ out, int C, int HW)
{
    __shared__ float t[32][33];
    const int b = blockIdx.z, c0 = blockIdx.y * 32, p0 = blockIdx.x * 32;
    const int tx = threadIdx.x & 31, ty = threadIdx.x >> 5;
#pragma unroll
    for (int r = 0; r < 4; r++)
        t[ty + 8 * r][tx] = in[((size_t)b * C + c0 + ty + 8 * r) * HW + p0 + tx];
    __syncthreads();
#pragma unroll
    for (int r = 0; r < 4; r++) {
        int p = p0 + ty + 8 * r;
        out[((size_t)b * HW + p) * C + c0 + tx] = __float2half_rn(t[tx][ty + 8 * r]);
    }
}

// ---------------- prep: conv1 weight OIHW -> [oc][tap*C + c] fp16 ----------------
__global__ __launch_bounds__(256) void wsplit_conv_aug(
    const float* __restrict__ w, h16* __restrict__ out, int C, int OC)
{
    int idx = blockIdx.x * 256 + threadIdx.x;
    int oc = idx / (9 * C); int rem = idx - oc * 9 * C;
    int tap = rem / C; int c = rem - tap * C;
    float v = (oc < OC) ? w[((size_t)oc * C + c) * 9 + tap] : 0.f;
    out[(size_t)oc * 9 * C + (size_t)tap * C + c] = __float2half_rn(v);
}

// ---------------- prep: conv2 weight, moving cin 0..511 only ----------------
__global__ __launch_bounds__(256) void wsplit_conv2(
    const float* __restrict__ w, h16* __restrict__ out)
{
    int idx = blockIdx.x * 256 + threadIdx.x;   // 1024 * 9 * 512
    int oc = idx / (9 * 512); int rem = idx - oc * 9 * 512;
    int tap = rem / 512; int c = rem - tap * 512;
    out[(size_t)oc * 4608 + (size_t)tap * 512 + c] =
        __float2half_rn(w[((size_t)oc * 1024 + c) * 9 + tap]);
}

// ---------------- merged small prep: c1a W fp16 + cls1 W fp16 ----------------
__global__ __launch_bounds__(256) void wsplit_small(
    const float* __restrict__ aw, const float* __restrict__ c1w,
    h16* __restrict__ W4, h16* __restrict__ W3)
{
    const int N4 = 64 * 9 * 256;
    int idx = blockIdx.x * 256 + threadIdx.x;
    if (idx < N4) {
        int oc = idx / (9 * 256); int rem = idx - oc * 9 * 256;
        int tap = rem / 256; int c = rem - tap * 256;
        float v = (oc < 48) ? aw[((size_t)oc * 256 + c) * 9 + tap] : 0.f;
        W4[(size_t)oc * 2304 + (size_t)tap * 256 + c] = __float2half_rn(v);
    } else {
        int i2 = idx - N4;
        if (i2 < 4992 * 1024) {
            int oc = i2 >> 10;
            float v = (oc < NOUT) ? c1w[i2] : 0.f;
            W3[i2] = __float2half_rn(v);
        }
    }
}

// ---------------- gp reduce over X1 fp16, deterministic ----------------
__global__ __launch_bounds__(512) void gp_reduce(
    const h16* __restrict__ X1, float* __restrict__ gp)
{
    const int b = blockIdx.x, c = threadIdx.x;    // c in [0,512)
    float s = 0.f;
    for (int p = 0; p < 256; p++)
        s += __half2float(X1[((size_t)(b * 256 + p)) * 512 + c]);
    gp[b * 512 + c] = s * (1.f / 256.f);
}

// ---------------- C9: per-(b, oc, boundary-class) gp correction ----------------
__global__ __launch_bounds__(128) void c9_kernel(
    const float* __restrict__ w, const float* __restrict__ gp, float* __restrict__ C9)
{
    __shared__ float sgp[512];
    __shared__ float sT[16][9];
    const int b = blockIdx.y, oc0 = blockIdx.x * 16, tid = threadIdx.x;
    for (int i = tid; i < 512; i += 128) sgp[i] = gp[b * 512 + i];
    __syncthreads();

    const int oc = oc0 + (tid >> 3), ln = tid & 7;
    float t[9];
#pragma unroll
    for (int k = 0; k < 9; k++) t[k] = 0.f;
    for (int c = ln * 64; c < ln * 64 + 64; c++) {
        float g = sgp[c];
        const float* wp = w + ((size_t)oc * 1024 + 512 + c) * 9;
#pragma unroll
        for (int k = 0; k < 9; k++) t[k] = fmaf(wp[k], g, t[k]);
    }
#pragma unroll
    for (int o = 4; o; o >>= 1)
#pragma unroll
        for (int k = 0; k < 9; k++) t[k] += __shfl_down_sync(0xffffffffu, t[k], o, 8);
    if (ln == 0)
#pragma unroll
        for (int k = 0; k < 9; k++) sT[tid >> 3][k] = t[k];
    __syncthreads();

    for (int i = tid; i < 144; i += 128) {
        int o = i / 9, cls = i - (i / 9) * 9;
        int fy = cls / 3, fx = cls - fy * 3;
        float s = 0.f;
#pragma unroll
        for (int ky = 0; ky < 3; ky++) {
            if ((fy == 0 && ky == 0) || (fy == 2 && ky == 2)) continue;
#pragma unroll
            for (int kx = 0; kx < 3; kx++) {
                if ((fx == 0 && kx == 0) || (fx == 2 && kx == 2)) continue;
                s += sT[o][ky * 3 + kx];
            }
        }
        C9[((size_t)b * 1024 + oc0 + o) * 9 + cls] = s;
    }
}

// =====================================================================
// fused: c1b + coord + cat-BN + MLP stages 0/1 (scalar) + stage 2 on HMMA.
// Stage 2: D^T = W2(256x16) x H1(64x16)^T via m16n8k16, exact-W 2-term
// (A'=[Wh|Wl], B'=[Hh|Hh], K'=32).  Channels = M rows -> coalesced
// float2 stores over pixel pairs.
// =====================================================================
__global__ __launch_bounds__(256) void fused_final(
    const float* __restrict__ cls1T, const float* __restrict__ c1aT,
    const float* __restrict__ c1b_w, const float* __restrict__ c1b_b,
    const float* __restrict__ cat_scale, const float* __restrict__ cat_shift,
    float* __restrict__ out)
{
    extern __shared__ __align__(16) char fsm[];
    float* sP  = (float*)fsm;                    // 4928 floats (19712 B)
    float* sWb = (float*)(fsm + 19712);          // 784 floats (3136 B)
    char*  U   = fsm + 19712 + 3136;
    float* sAc = (float*)U;                      // 48*64 (12288 B)
    float* sI  = (float*)(U + 12288);            // 18*64 (4608 B)
    float* sH0 = (float*)(U + 16896);            // 16*64 (4096 B)
    float* sH1 = (float*)(U + 20992);            // 16*64 (4096 B)
    char*  sAw = U;                              // late: 256 rows x 80 B (20480)
    char*  sB  = U + 25088;                      // late: 64 rows x 80 B (5120)
    // total = 19712 + 3136 + 30208 = 53056 B

    const int b = blockIdx.y, lpos = blockIdx.x;
    const int ly = lpos >> 4, lx = lpos & 15;
    const int tid = threadIdx.x;
    const int px = tid & 63, q = tid >> 6;
    const int py = px >> 3, pxx = px & 7;
    const int lane = tid & 31;

    const float* pp = cls1T + (size_t)(b * 256 + lpos) * NOUT;
    for (int i = tid; i < NOUT; i += 256) sP[i] = pp[i];
    for (int i = tid; i < 48 * 64; i += 256) {
        int p = i / 48, ch = i - p * 48;
        int yy = ly * 8 + (p >> 3), xx = lx * 8 + (p & 7);
        sAc[ch * 64 + p] = c1aT[((size_t)b * 16384 + yy * 128 + xx) * 48 + ch];
    }
    for (int i = tid; i < 768; i += 256) sWb[i] = c1b_w[i];
    if (tid < 16) sWb[768 + tid] = c1b_b[tid];
    __syncthreads();

    // c1b + cat-BN -> sI (channels 2..17); coords -> 0,1
#pragma unroll
    for (int jj = 0; jj < 4; jj++) {
        int j = q * 4 + jj;
        float s = sWb[768 + j];
#pragma unroll
        for (int c = 0; c < 48; c++)
            s = fmaf(sAc[c * 64 + px], sWb[j * 48 + c], s);
        sI[(2 + j) * 64 + px] = fmaf(s, cat_scale[2 + j], cat_shift[2 + j]);
    }
    if (q == 0) {
        sI[px]      = fmaf((float)pxx * 0.125f, cat_scale[0], cat_shift[0]);
        sI[64 + px] = fmaf((float)py  * 0.125f, cat_scale[1], cat_shift[1]);
    }
    __syncthreads();

    // stage 0: 18 -> 16 relu
#pragma unroll
    for (int jj = 0; jj < 4; jj++) {
        int o = q * 4 + jj;
        float s = sP[288 + o];
#pragma unroll
        for (int c = 0; c < 18; c++)
            s = fmaf(sP[o * 18 + c], sI[c * 64 + px], s);
        sH0[o * 64 + px] = fmaxf(s, 0.f);
    }
    __syncthreads();

    // stage 1: 16 -> 16 relu
#pragma unroll
    for (int jj = 0; jj < 4; jj++) {
        int o = q * 4 + jj;
        float s = sP[560 + o];
#pragma unroll
        for (int c = 0; c < 16; c++)
            s = fmaf(sP[304 + o * 16 + c], sH0[c * 64 + px], s);
        sH1[o * 64 + px] = fmaxf(s, 0.f);
    }
    __syncthreads();

    // build fp16 operands: sB (H, 64 px rows, k=c dup at 16+c); sAw (W2 hi|lo)
    for (int t = tid; t < 1024; t += 256) {
        int p2 = t & 63, c = t >> 6;
        h16 hh = __float2half_rn(sH1[c * 64 + p2]);
        *(h16*)(sB + p2 * 80 + c * 2) = hh;
        *(h16*)(sB + p2 * 80 + 32 + c * 2) = hh;
    }
    for (int t = tid; t < 4096; t += 256) {
        int o = t >> 4, c = t & 15;
        float w = sP[576 + t];
        h16 wh = __float2half_rn(w);
        h16 wl = __float2half_rn(w - __half2float(wh));
        *(h16*)(sAw + o * 80 + c * 2) = wh;
        *(h16*)(sAw + o * 80 + 32 + c * 2) = wl;
    }
    __syncthreads();

    // stage 2 MMA: 256(ch) x 64(px) x 32
    const int warp = tid >> 5;
    const int m0 = warp * 32;
    const unsigned sAb = s2u(sAw), sBb = s2u(sB);
    float acc[2][8][4];
#pragma unroll
    for (int a = 0; a < 2; a++)
#pragma unroll
        for (int n2 = 0; n2 < 8; n2++)
#pragma unroll
            for (int c = 0; c < 4; c++) acc[a][n2][c] = 0.f;

#pragma unroll
    for (int step = 0; step < 2; step++) {
        unsigned af[2][4], bfr[4][4];
        int ch = step * 2 + (lane >> 4);
#pragma unroll
        for (int i = 0; i < 2; i++)
            ldm4(af[i], sAb + (m0 + 16 * i + (lane & 15)) * 80 + ch * 16);
        int rr = (lane & 7) + ((lane >> 4) << 3);
        int chB = step * 2 + ((lane >> 3) & 1);
#pragma unroll
        for (int i = 0; i < 4; i++)
            ldm4(bfr[i], sBb + (16 * i + rr) * 80 + chB * 16);
#pragma unroll
        for (int mt = 0; mt < 2; mt++)
#pragma unroll
            for (int nt = 0; nt < 8; nt++)
                mma16816(acc[mt][nt], af[mt], &bfr[nt >> 1][(nt & 1) * 2]);
    }

    // epilogue: + bias, coalesced float2 stores (pixel pairs)
    float* obase = out + ((size_t)b << 22) + (ly * 8) * 128 + lx * 8;
#pragma unroll
    for (int mt = 0; mt < 2; mt++)
#pragma unroll
        for (int nt = 0; nt < 8; nt++) {
            float* d = acc[mt][nt];
            int o = m0 + mt * 16 + (lane >> 2);
            int pxx2 = (lane & 3) * 2;     // pixel within row; row = nt
#pragma unroll
            for (int h2 = 0; h2 < 2; h2++) {
                int oo = o + h2 * 8;
                float bv = sP[4672 + oo];
                float2 v = make_float2(d[h2 * 2] + bv, d[h2 * 2 + 1] + bv);
                *(float2*)(obase + ((size_t)oo << 14) + nt * 128 + pxx2) = v;
            }
        }
}

// ---------------- host launcher ----------------
extern "C" void kernel_launch(void* const* d_in, const int* in_sizes, int n_in,
                              void* d_out, int out_size)
{
    const float* res5 = (const float*)d_in[0];
    const float* res2 = (const float*)d_in[1];
    const float* bw   = (const float*)d_in[2];
    const float* bn1s = (const float*)d_in[3];
    const float* bn1h = (const float*)d_in[4];
    const float* c0w  = (const float*)d_in[5];
    const float* bn2s = (const float*)d_in[6];
    const float* bn2h = (const float*)d_in[7];
    const float* c1w  = (const float*)d_in[8];
    const float* c1b  = (const float*)d_in[9];
    const float* aw   = (const float*)d_in[10];
    const float* bn3s = (const float*)d_in[11];
    const float* bn3h = (const float*)d_in[12];
    const float* bw2  = (const float*)d_in[13];
    const float* bb2  = (const float*)d_in[14];
    const float* cats = (const float*)d_in[15];
    const float* cath = (const float*)d_in[16];
    float* out = (float*)d_out;

    h16 *Xs5, *W1, *X1, *W2, *X2, *W3, *Xr2, *W4;
    float *gp, *C9, *cls1T, *c1aT;
    cudaGetSymbolAddress((void**)&Xs5, g_Xs5);
    cudaGetSymbolAddress((void**)&W1,  g_W1);
    cudaGetSymbolAddress((void**)&X1,  g_X1);
    cudaGetSymbolAddress((void**)&W2,  g_W2);
    cudaGetSymbolAddress((void**)&X2,  g_X2);
    cudaGetSymbolAddress((void**)&W3,  g_W3);
    cudaGetSymbolAddress((void**)&Xr2, g_Xr2);
    cudaGetSymbolAddress((void**)&W4,  g_W4);
    cudaGetSymbolAddress((void**)&gp,  g_gp);
    cudaGetSymbolAddress((void**)&C9,  g_C9);
    cudaGetSymbolAddress((void**)&cls1T, g_cls1T);
    cudaGetSymbolAddress((void**)&c1aT,  g_c1aT);

    const int SM_C1 = (128 + 64) * 144 * 3;    // 82944
    const int SM_BB = (128 + 128) * 144 * 3;   // 110592
    const int SM_C4 = (128 + 48) * 144 * 3;    // 76032
    const int SM_FF = 53056;
    cudaFuncSetAttribute(gemm_mma<128, 64, 2, true>,   cudaFuncAttributeMaxDynamicSharedMemorySize, SM_C1);
    cudaFuncSetAttribute(gemm_mma<128, 128, 2, true>,  cudaFuncAttributeMaxDynamicSharedMemorySize, SM_BB);
    cudaFuncSetAttribute(gemm_mma<128, 128, 2, false>, cudaFuncAttributeMaxDynamicSharedMemorySize, SM_BB);
    cudaFuncSetAttribute(gemm_mma<128, 48, 1, true>,   cudaFuncAttributeMaxDynamicSharedMemorySize, SM_C4);
    cudaFuncSetAttribute(fused_final,                  cudaFuncAttributeMaxDynamicSharedMemorySize, SM_FF);

    // 1) res5 -> fp16 [pos][2048]
    split_aug<<<dim3(8, 64, 8), 256>>>(res5, Xs5, 2048, 256);
    // 2) conv1 weights -> fp16
    wsplit_conv_aug<<<(512 * 9 * 2048) / 256, 256>>>(bw, W1, 2048, 512);
    // 3) conv1 GEMM: K = 18432, split-K x3 -> partials
    gemm_mma<128, 64, 2, true><<<dim3(8, 16, 3), 256, SM_C1>>>(
        Xs5, W1, 2048, 16, 16, 96, 18432, 4, 512,
        nullptr, nullptr, nullptr, cls1T, 512);
    // 4) reduce -> X1 fp16
    reduce_aug<<<(2048 * 512 / 4) / 256, 256>>>(cls1T, 3, 2048, 512, nullptr, bn1s, bn1h, X1);
    // 5) global pool
    gp_reduce<<<8, 512>>>(X1, gp);
    // 6) C9 correction table
    c9_kernel<<<dim3(64, 8), 128>>>(c0w, gp, C9);
    // 7) conv2 weights -> fp16
    wsplit_conv2<<<(1024 * 9 * 512) / 256, 256>>>(c0w, W2);
    // 8) conv2 GEMM: K = 4608, split-K x2
    gemm_mma<128, 128, 2, true><<<dim3(8, 16, 2), 256, SM_BB>>>(
        X1, W2, 512, 16, 16, 36, 4608, 4, 1024,
        nullptr, nullptr, nullptr, cls1T, 1024);
    // 9) reduce (+C9) -> X2 fp16 (single)
    reduce_aug<<<(2048 * 1024 / 4) / 256, 256>>>(cls1T, 2, 2048, 1024, C9, bn2s, bn2h, X2);
    // 10) small weights: c1a fp16 + cls1 fp16
    wsplit_small<<<(64 * 9 * 256 + 4992 * 1024 + 255) / 256, 256>>>(aw, c1w, W4, W3);
    // 11) cls1 GEMM: K = 1024 (16 chunks) -> cls1T fp32
    gemm_mma<128, 128, 2, false><<<dim3(39, 16, 1), 256, SM_BB>>>(
        X2, W3, 1024, 16, 16, 16, 1024, 1, NOUT,
        nullptr, nullptr, c1b, cls1T, NOUT);
    // 12) res2 -> fp16
    split_aug<<<dim3(512, 8, 8), 256>>>(res2, Xr2, 256, 16384);
    // 13) c1a GEMM: K = 2304 (36 chunks) -> c1aT fp32
    gemm_mma<128, 48, 1, true><<<dim3(1, 1024, 1), 256, SM_C4>>>(
        Xr2, W4, 256, 128, 128, 36, 2304, 2, 48,
        bn3s, bn3h, nullptr, c1aT, 48);
    // 14) fused tail (HMMA stage-2)
    fused_final<<<dim3(256, 8), 256, SM_FF>>>(cls1T, c1aT, bw2, bb2, cats, cath, out);
}

// round 13
// speedup vs baseline: 2.6747x; 1.0163x over previous
#include <cuda_runtime.h>
#include <cuda_fp16.h>
#include <cstdint>

typedef __half h16;
#define NOUT 4928

// ---------------- scratch (device globals; sizes in elements) ----------------
__device__ __align__(16) h16 g_Xs5[(size_t)2048 * 2048];     // res5 fp16 [pos][2048]
__device__ __align__(16) h16 g_W1 [(size_t)512 * 18432];     // conv1 W fp16
__device__ __align__(16) h16 g_X1 [(size_t)2048 * 512];      // x1 fp16
__device__ __align__(16) h16 g_W2 [(size_t)1024 * 4608];     // conv2 W fp16 (moving 512 cin)
__device__ __align__(16) h16 g_X2 [(size_t)2048 * 1024];     // x2 fp16 (single)
__device__ __align__(16) h16 g_W3 [(size_t)4992 * 1024];     // cls1 W fp16 (oc padded)
__device__ __align__(16) h16 g_Xr2[(size_t)131072 * 256];    // res2 fp16
__device__ __align__(16) h16 g_W4 [(size_t)64 * 2304];       // c1a W fp16
__device__ float g_gp [8 * 512];
__device__ float g_C9 [(size_t)8 * 1024 * 9];
__device__ float g_cls1T[(size_t)2048 * NOUT];               // also split-K partial buffer
__device__ float g_c1aT [(size_t)131072 * 48];

// ---------------- helpers ----------------
__device__ __forceinline__ unsigned s2u(const void* p) {
    return (unsigned)__cvta_generic_to_shared(p);
}
__device__ __forceinline__ void cpa16(unsigned d, const void* s, unsigned sz) {
    asm volatile("cp.async.ca.shared.global [%0], [%1], 16, %2;" :: "r"(d), "l"(s), "r"(sz));
}
__device__ __forceinline__ void cpa_commit() {
    asm volatile("cp.async.commit_group;" ::: "memory");
}
template<int N> __device__ __forceinline__ void cpa_wait() {
    asm volatile("cp.async.wait_group %0;" :: "n"(N) : "memory");
}
__device__ __forceinline__ void ldm4(unsigned* r, unsigned a) {
    asm volatile("ldmatrix.sync.aligned.m8n8.x4.shared.b16 {%0,%1,%2,%3}, [%4];"
        : "=r"(r[0]), "=r"(r[1]), "=r"(r[2]), "=r"(r[3]) : "r"(a));
}
__device__ __forceinline__ void mma16816(float* d, const unsigned* a, const unsigned* b) {
    asm volatile("mma.sync.aligned.m16n8k16.row.col.f32.f16.f16.f32 "
        "{%0,%1,%2,%3}, {%4,%5,%6,%7}, {%8,%9}, {%0,%1,%2,%3};"
        : "+f"(d[0]), "+f"(d[1]), "+f"(d[2]), "+f"(d[3])
        : "r"(a[0]), "r"(a[1]), "r"(a[2]), "r"(a[3]), "r"(b[0]), "r"(b[1]));
}

// =====================================================================
// HMMA fp16 GEMM: BK=64, 3-stage cp.async pipeline, 2 CTAs/SM.
// epi: 1 = +bias -> fp32 (guarded); 2 = BN+ReLU -> fp32 (guarded);
//      4 = raw fp32 split-K partial at [blockIdx.z][M][ofc]
// =====================================================================
template<int BM, int BN, int WS, bool CONV3>
__global__ __launch_bounds__(256, 2) void gemm_mma(
    const h16* __restrict__ A, const h16* __restrict__ B,
    int C3, int imh, int imw, int nk, int Kb,
    int epi, int nvalid,
    const float* __restrict__ scale, const float* __restrict__ shift,
    const float* __restrict__ bias,
    float* __restrict__ Of, int ofc)
{
    constexpr int WM = BM / (8 / WS), WN = BN / WS;
    constexpr int MT = WM / 16;
    constexpr int NT = WN / 8;
    constexpr int NF = WN / 16;
    constexpr int AJ = BM / 32;
    constexpr int BJ = (BN * 8 + 255) / 256;
    constexpr int ABYTES = BM * 144, STG = (BM + BN) * 144;

    extern __shared__ __align__(16) char sm[];
    const int tid = threadIdx.x;
    const int nb = blockIdx.x, mtile = blockIdx.y;
    const int kzoff = blockIdx.z * nk;
    const int warp = tid >> 5, lane = tid & 31;
    const int m0 = (warp / WS) * WM, n0 = (warp % WS) * WN;
    const unsigned sbase = s2u(sm);
    const int imgpix = imh * imw;
    const int vec = tid & 7;

    int arow[AJ], ay[AJ], ax[AJ], apb[AJ];
#pragma unroll
    for (int j = 0; j < AJ; j++) {
        arow[j] = (tid >> 3) + j * 32;
        int g = mtile * BM + arow[j];
        if (CONV3) {
            int bb = g / imgpix, lp = g - bb * imgpix;
            ay[j] = lp / imw; ax[j] = lp - ay[j] * imw; apb[j] = bb * imgpix;
        } else { ay[j] = 0; ax[j] = 0; apb[j] = g; }
    }

    auto load_chunk = [&](int kc, int st) {
        unsigned Ab = sbase + st * STG;
        unsigned Bb = Ab + ABYTES;
        int k0 = (kzoff + kc) * 64;
        int dy = 0, dx = 0, cb = k0;
        if (CONV3) {
            int rk = k0 / C3; cb = k0 - rk * C3;
            int r3 = rk / 3; dy = r3 - 1; dx = rk - r3 * 3 - 1;
        }
#pragma unroll
        for (int j = 0; j < AJ; j++) {
            const h16* src;
            unsigned sz = 16;
            if (CONV3) {
                int y2 = ay[j] + dy, x2 = ax[j] + dx;
                bool v = ((unsigned)y2 < (unsigned)imh) && ((unsigned)x2 < (unsigned)imw);
                src = A + (size_t)(apb[j] + y2 * imw + x2) * C3 + cb + vec * 8;
                if (!v) { src = A; sz = 0; }
            } else {
                src = A + (size_t)apb[j] * C3 + k0 + vec * 8;
            }
            cpa16(Ab + arow[j] * 144 + vec * 16, src, sz);
        }
#pragma unroll
        for (int j = 0; j < BJ; j++) {
            int item = tid + 256 * j;
            int row = item >> 3;
            if ((BN * 8 % 256 == 0) || item < BN * 8)
                cpa16(Bb + row * 144 + (item & 7) * 16,
                      B + (size_t)(nb * BN + row) * Kb + k0 + (item & 7) * 8, 16);
        }
    };

    float acc[MT][NT][4];
#pragma unroll
    for (int a = 0; a < MT; a++)
#pragma unroll
        for (int b2 = 0; b2 < NT; b2++)
#pragma unroll
            for (int c = 0; c < 4; c++) acc[a][b2][c] = 0.f;

    auto compute = [&](int st) {
        unsigned Ab = sbase + st * STG;
        unsigned Bb = Ab + ABYTES;
#pragma unroll
        for (int step = 0; step < 4; step++) {
            unsigned af[MT][4], bfr[NF][4];
            {
                int ch = step * 2 + (lane >> 4);
#pragma unroll
                for (int i = 0; i < MT; i++)
                    ldm4(af[i], Ab + (m0 + 16 * i + (lane & 15)) * 144 + ch * 16);
            }
            {
                int rr = (lane & 7) + ((lane >> 4) << 3);
                int ch = step * 2 + ((lane >> 3) & 1);
#pragma unroll
                for (int i = 0; i < NF; i++)
                    ldm4(bfr[i], Bb + (n0 + 16 * i + rr) * 144 + ch * 16);
            }
#pragma unroll
            for (int mt = 0; mt < MT; mt++)
#pragma unroll
                for (int nt = 0; nt < NT; nt++)
                    mma16816(acc[mt][nt], af[mt], &bfr[nt >> 1][(nt & 1) * 2]);
        }
    };

    load_chunk(0, 0);
    cpa_commit();
    if (nk > 1) load_chunk(1, 1);
    cpa_commit();
    int st2 = 2;
    for (int kc = 0; kc < nk; kc++) {
        cpa_wait<1>();
        __syncthreads();
        if (kc + 2 < nk) {
            load_chunk(kc + 2, st2);
            if (++st2 == 3) st2 = 0;
        }
        cpa_commit();
        compute(kc % 3);
    }

    // ---- epilogue ----
    float* dstz = Of;
    if (epi == 4)
        dstz = Of + (size_t)blockIdx.z * ((size_t)gridDim.y * BM) * ofc;
#pragma unroll
    for (int mt = 0; mt < MT; mt++)
#pragma unroll
        for (int nt = 0; nt < NT; nt++) {
            float* d = acc[mt][nt];
            int row = mtile * BM + m0 + mt * 16 + (lane >> 2);
            int col = nb * BN + n0 + nt * 8 + (lane & 3) * 2;
#pragma unroll
            for (int h = 0; h < 2; h++) {
                int r = row + h * 8;
                float v0 = d[h * 2 + 0], v1 = d[h * 2 + 1];
                if (epi == 4) {
                    *(float2*)(dstz + (size_t)r * ofc + col) = make_float2(v0, v1);
                } else if (epi == 1) {
                    if (col < nvalid) {
                        float2 o = make_float2(v0 + bias[col], v1 + bias[col + 1]);
                        *(float2*)(Of + (size_t)r * ofc + col) = o;
                    }
                } else {
                    if (col < nvalid) {
                        float2 o;
                        o.x = fmaxf(fmaf(v0, scale[col], shift[col]), 0.f);
                        o.y = fmaxf(fmaf(v1, scale[col + 1], shift[col + 1]), 0.f);
                        *(float2*)(Of + (size_t)r * ofc + col) = o;
                    }
                }
            }
        }
}

// ---------------- reduce split-K partials + (opt C9) + BN/ReLU -> fp16 ----------------
__global__ __launch_bounds__(256) void reduce_aug(
    const float* __restrict__ P, int ns, int M, int C,
    const float* __restrict__ corr,
    const float* __restrict__ scale, const float* __restrict__ shift,
    h16* __restrict__ out)
{
    int idx = (blockIdx.x * 256 + threadIdx.x) * 4;
    int r = idx / C, col = idx - r * C;
    if (r >= M) return;
    float4 v = *(const float4*)(P + (size_t)r * C + col);
    for (int s = 1; s < ns; s++) {
        float4 p = *(const float4*)(P + ((size_t)s * M + r) * C + col);
        v.x += p.x; v.y += p.y; v.z += p.z; v.w += p.w;
    }
    if (corr) {
        int lp = r & 255, y = lp >> 4, xp = lp & 15;
        int cls = ((y == 0) ? 0 : ((y == 15) ? 6 : 3))
                + ((xp == 0) ? 0 : ((xp == 15) ? 2 : 1));
        const float* cp = corr + (size_t)(r >> 8) * 1024 * 9 + (size_t)col * 9 + cls;
        v.x += cp[0]; v.y += cp[9]; v.z += cp[18]; v.w += cp[27];
    }
    float4 sc = *(const float4*)(scale + col);
    float4 sh = *(const float4*)(shift + col);
    v.x = fmaxf(fmaf(v.x, sc.x, sh.x), 0.f);
    v.y = fmaxf(fmaf(v.y, sc.y, sh.y), 0.f);
    v.z = fmaxf(fmaf(v.z, sc.z, sh.z), 0.f);
    v.w = fmaxf(fmaf(v.w, sc.w, sh.w), 0.f);
    ushort4 u;
    u.x = __half_as_ushort(__float2half_rn(v.x));
    u.y = __half_as_ushort(__float2half_rn(v.y));
    u.z = __half_as_ushort(__float2half_rn(v.z));
    u.w = __half_as_ushort(__float2half_rn(v.w));
    *(ushort4*)(out + (size_t)r * C + col) = u;
}

// =====================================================================
// Unified prep: one launch does both activation transposes + all weight
// conversions. Segments by blockIdx.x:
//   [0, 4096)            res5 NCHW->posmajor fp16 (32x32 smem transpose)
//   [4096, 36864)        res2 same
//   [36864, 37376)       conv1 W: [oc][c][tap] -> [oc][tap*2048+c], coalesced
//   [37376, 38400)       conv2 W: cin 0..511 only, same scheme
//   [38400, 58944)       c1a W + cls1 W, elementwise
// =====================================================================
__global__ __launch_bounds__(256) void prep_all(
    const float* __restrict__ res5, const float* __restrict__ res2,
    const float* __restrict__ bw,   const float* __restrict__ c0w,
    const float* __restrict__ aw,   const float* __restrict__ c1w,
    h16* __restrict__ Xs5, h16* __restrict__ Xr2,
    h16* __restrict__ W1,  h16* __restrict__ W2,
    h16* __restrict__ W4,  h16* __restrict__ W3)
{
    __shared__ float tt[32][33];
    __shared__ float tw[9][132];
    const int blk = blockIdx.x, tid = threadIdx.x;
    const int tx = tid & 31, ty = tid >> 5;

    if (blk < 36864) {
        // activation transpose segments
        const float* in; h16* out; int C, HW, b, c0, p0;
        if (blk < 4096) {
            in = res5; out = Xs5; C = 2048; HW = 256;
            p0 = (blk & 7) * 32; c0 = ((blk >> 3) & 63) * 32; b = blk >> 9;
        } else {
            int l = blk - 4096;
            in = res2; out = Xr2; C = 256; HW = 16384;
            p0 = (l & 511) * 32; c0 = ((l >> 9) & 7) * 32; b = l >> 12;
        }
#pragma unroll
        for (int r = 0; r < 4; r++)
            tt[ty + 8 * r][tx] = in[((size_t)b * C + c0 + ty + 8 * r) * HW + p0 + tx];
        __syncthreads();
#pragma unroll
        for (int r = 0; r < 4; r++) {
            int p = p0 + ty + 8 * r;
            out[((size_t)b * HW + p) * C + c0 + tx] = __float2half_rn(tt[tx][ty + 8 * r]);
        }
    } else if (blk < 38400) {
        // conv weight transpose, staged through smem for coalesced reads
        const float* wsrc; h16* wdst; int C, CI, ntile, oc;
        if (blk < 37376) { oc = blk - 36864; wsrc = bw;  wdst = W1; C = 2048; CI = 2048; ntile = 16; }
        else             { oc = blk - 37376; wsrc = c0w; wdst = W2; C = 512;  CI = 1024; ntile = 4; }
        for (int ct = 0; ct < ntile; ct++) {
            int c0 = ct * 128;
            // read 128 channels x 9 taps, coalesced over input layout [oc][CI][9]
            for (int i = tid; i < 1152; i += 256) {
                int c = i / 9, tap = i - c * 9;
                tw[tap][c] = wsrc[(size_t)oc * CI * 9 + (size_t)(c0 + c) * 9 + tap];
            }
            __syncthreads();
            // write tap-major halves, coalesced
            for (int i = tid; i < 1152; i += 256) {
                int tap = i >> 7, c = i & 127;
                wdst[(size_t)oc * 9 * C + (size_t)tap * C + c0 + c] =
                    __float2half_rn(tw[tap][c]);
            }
            __syncthreads();
        }
    } else {
        // small weights, elementwise
        const int N4 = 64 * 9 * 256;
        int idx = (blk - 38400) * 256 + tid;
        if (idx < N4) {
            int oc = idx / (9 * 256); int rem = idx - oc * 9 * 256;
            int tap = rem / 256; int c = rem - tap * 256;
            float v = (oc < 48) ? aw[((size_t)oc * 256 + c) * 9 + tap] : 0.f;
            W4[(size_t)oc * 2304 + (size_t)tap * 256 + c] = __float2half_rn(v);
        } else {
            int i2 = idx - N4;
            if (i2 < 4992 * 1024) {
                int oc = i2 >> 10;
                float v = (oc < NOUT) ? c1w[i2] : 0.f;
                W3[i2] = __float2half_rn(v);
            }
        }
    }
}

// ---------------- gp reduce over X1 fp16, deterministic ----------------
__global__ __launch_bounds__(512) void gp_reduce(
    const h16* __restrict__ X1, float* __restrict__ gp)
{
    const int b = blockIdx.x, c = threadIdx.x;    // c in [0,512)
    float s = 0.f;
    for (int p = 0; p < 256; p++)
        s += __half2float(X1[((size_t)(b * 256 + p)) * 512 + c]);
    gp[b * 512 + c] = s * (1.f / 256.f);
}

// ---------------- C9: per-(b, oc, boundary-class) gp correction ----------------
__global__ __launch_bounds__(128) void c9_kernel(
    const float* __restrict__ w, const float* __restrict__ gp, float* __restrict__ C9)
{
    __shared__ float sgp[512];
    __shared__ float sT[16][9];
    const int b = blockIdx.y, oc0 = blockIdx.x * 16, tid = threadIdx.x;
    for (int i = tid; i < 512; i += 128) sgp[i] = gp[b * 512 + i];
    __syncthreads();

    const int oc = oc0 + (tid >> 3), ln = tid & 7;
    float t[9];
#pragma unroll
    for (int k = 0; k < 9; k++) t[k] = 0.f;
    for (int c = ln * 64; c < ln * 64 + 64; c++) {
        float g = sgp[c];
        const float* wp = w + ((size_t)oc * 1024 + 512 + c) * 9;
#pragma unroll
        for (int k = 0; k < 9; k++) t[k] = fmaf(wp[k], g, t[k]);
    }
#pragma unroll
    for (int o = 4; o; o >>= 1)
#pragma unroll
        for (int k = 0; k < 9; k++) t[k] += __shfl_down_sync(0xffffffffu, t[k], o, 8);
    if (ln == 0)
#pragma unroll
        for (int k = 0; k < 9; k++) sT[tid >> 3][k] = t[k];
    __syncthreads();

    for (int i = tid; i < 144; i += 128) {
        int o = i / 9, cls = i - (i / 9) * 9;
        int fy = cls / 3, fx = cls - fy * 3;
        float s = 0.f;
#pragma unroll
        for (int ky = 0; ky < 3; ky++) {
            if ((fy == 0 && ky == 0) || (fy == 2 && ky == 2)) continue;
#pragma unroll
            for (int kx = 0; kx < 3; kx++) {
                if ((fx == 0 && kx == 0) || (fx == 2 && kx == 2)) continue;
                s += sT[o][ky * 3 + kx];
            }
        }
        C9[((size_t)b * 1024 + oc0 + o) * 9 + cls] = s;
    }
}

// =====================================================================
// fused: c1b + coord + cat-BN + MLP stages 0/1 (scalar) + stage 2 on HMMA.
// =====================================================================
__global__ __launch_bounds__(256) void fused_final(
    const float* __restrict__ cls1T, const float* __restrict__ c1aT,
    const float* __restrict__ c1b_w, const float* __restrict__ c1b_b,
    const float* __restrict__ cat_scale, const float* __restrict__ cat_shift,
    float* __restrict__ out)
{
    extern __shared__ __align__(16) char fsm[];
    float* sP  = (float*)fsm;                    // 4928 floats
    float* sWb = (float*)(fsm + 19712);          // 784 floats
    char*  U   = fsm + 19712 + 3136;
    float* sAc = (float*)U;                      // 48*64
    float* sI  = (float*)(U + 12288);            // 18*64
    float* sH0 = (float*)(U + 16896);            // 16*64
    float* sH1 = (float*)(U + 20992);            // 16*64
    char*  sAw = U;                              // late: 256 x 80B
    char*  sB  = U + 25088;                      // late: 64 x 80B

    const int b = blockIdx.y, lpos = blockIdx.x;
    const int ly = lpos >> 4, lx = lpos & 15;
    const int tid = threadIdx.x;
    const int px = tid & 63, q = tid >> 6;
    const int py = px >> 3, pxx = px & 7;
    const int lane = tid & 31;

    const float* pp = cls1T + (size_t)(b * 256 + lpos) * NOUT;
    for (int i = tid; i < NOUT; i += 256) sP[i] = pp[i];
    for (int i = tid; i < 48 * 64; i += 256) {
        int p = i / 48, ch = i - p * 48;
        int yy = ly * 8 + (p >> 3), xx = lx * 8 + (p & 7);
        sAc[ch * 64 + p] = c1aT[((size_t)b * 16384 + yy * 128 + xx) * 48 + ch];
    }
    for (int i = tid; i < 768; i += 256) sWb[i] = c1b_w[i];
    if (tid < 16) sWb[768 + tid] = c1b_b[tid];
    __syncthreads();

#pragma unroll
    for (int jj = 0; jj < 4; jj++) {
        int j = q * 4 + jj;
        float s = sWb[768 + j];
#pragma unroll
        for (int c = 0; c < 48; c++)
            s = fmaf(sAc[c * 64 + px], sWb[j * 48 + c], s);
        sI[(2 + j) * 64 + px] = fmaf(s, cat_scale[2 + j], cat_shift[2 + j]);
    }
    if (q == 0) {
        sI[px]      = fmaf((float)pxx * 0.125f, cat_scale[0], cat_shift[0]);
        sI[64 + px] = fmaf((float)py  * 0.125f, cat_scale[1], cat_shift[1]);
    }
    __syncthreads();

#pragma unroll
    for (int jj = 0; jj < 4; jj++) {
        int o = q * 4 + jj;
        float s = sP[288 + o];
#pragma unroll
        for (int c = 0; c < 18; c++)
            s = fmaf(sP[o * 18 + c], sI[c * 64 + px], s);
        sH0[o * 64 + px] = fmaxf(s, 0.f);
    }
    __syncthreads();

#pragma unroll
    for (int jj = 0; jj < 4; jj++) {
        int o = q * 4 + jj;
        float s = sP[560 + o];
#pragma unroll
        for (int c = 0; c < 16; c++)
            s = fmaf(sP[304 + o * 16 + c], sH0[c * 64 + px], s);
        sH1[o * 64 + px] = fmaxf(s, 0.f);
    }
    __syncthreads();

    for (int t = tid; t < 1024; t += 256) {
        int p2 = t & 63, c = t >> 6;
        h16 hh = __float2half_rn(sH1[c * 64 + p2]);
        *(h16*)(sB + p2 * 80 + c * 2) = hh;
        *(h16*)(sB + p2 * 80 + 32 + c * 2) = hh;
    }
    for (int t = tid; t < 4096; t += 256) {
        int o = t >> 4, c = t & 15;
        float w = sP[576 + t];
        h16 wh = __float2half_rn(w);
        h16 wl = __float2half_rn(w - __half2float(wh));
        *(h16*)(sAw + o * 80 + c * 2) = wh;
        *(h16*)(sAw + o * 80 + 32 + c * 2) = wl;
    }
    __syncthreads();

    const int warp = tid >> 5;
    const int m0 = warp * 32;
    const unsigned sAb = s2u(sAw), sBb = s2u(sB);
    float acc[2][8][4];
#pragma unroll
    for (int a = 0; a < 2; a++)
#pragma unroll
        for (int n2 = 0; n2 < 8; n2++)
#pragma unroll
            for (int c = 0; c < 4; c++) acc[a][n2][c] = 0.f;

#pragma unroll
    for (int step = 0; step < 2; step++) {
        unsigned af[2][4], bfr[4][4];
        int ch = step * 2 + (lane >> 4);
#pragma unroll
        for (int i = 0; i < 2; i++)
            ldm4(af[i], sAb + (m0 + 16 * i + (lane & 15)) * 80 + ch * 16);
        int rr = (lane & 7) + ((lane >> 4) << 3);
        int chB = step * 2 + ((lane >> 3) & 1);
#pragma unroll
        for (int i = 0; i < 4; i++)
            ldm4(bfr[i], sBb + (16 * i + rr) * 80 + chB * 16);
#pragma unroll
        for (int mt = 0; mt < 2; mt++)
#pragma unroll
            for (int nt = 0; nt < 8; nt++)
                mma16816(acc[mt][nt], af[mt], &bfr[nt >> 1][(nt & 1) * 2]);
    }

    float* obase = out + ((size_t)b << 22) + (ly * 8) * 128 + lx * 8;
#pragma unroll
    for (int mt = 0; mt < 2; mt++)
#pragma unroll
        for (int nt = 0; nt < 8; nt++) {
            float* d = acc[mt][nt];
            int o = m0 + mt * 16 + (lane >> 2);
            int pxx2 = (lane & 3) * 2;
#pragma unroll
            for (int h2 = 0; h2 < 2; h2++) {
                int oo = o + h2 * 8;
                float bv = sP[4672 + oo];
                float2 v = make_float2(d[h2 * 2] + bv, d[h2 * 2 + 1] + bv);
                *(float2*)(obase + ((size_t)oo << 14) + nt * 128 + pxx2) = v;
            }
        }
}

// ---------------- host launcher ----------------
extern "C" void kernel_launch(void* const* d_in, const int* in_sizes, int n_in,
                              void* d_out, int out_size)
{
    const float* res5 = (const float*)d_in[0];
    const float* res2 = (const float*)d_in[1];
    const float* bw   = (const float*)d_in[2];
    const float* bn1s = (const float*)d_in[3];
    const float* bn1h = (const float*)d_in[4];
    const float* c0w  = (const float*)d_in[5];
    const float* bn2s = (const float*)d_in[6];
    const float* bn2h = (const float*)d_in[7];
    const float* c1w  = (const float*)d_in[8];
    const float* c1b  = (const float*)d_in[9];
    const float* aw   = (const float*)d_in[10];
    const float* bn3s = (const float*)d_in[11];
    const float* bn3h = (const float*)d_in[12];
    const float* bw2  = (const float*)d_in[13];
    const float* bb2  = (const float*)d_in[14];
    const float* cats = (const float*)d_in[15];
    const float* cath = (const float*)d_in[16];
    float* out = (float*)d_out;

    h16 *Xs5, *W1, *X1, *W2, *X2, *W3, *Xr2, *W4;
    float *gp, *C9, *cls1T, *c1aT;
    cudaGetSymbolAddress((void**)&Xs5, g_Xs5);
    cudaGetSymbolAddress((void**)&W1,  g_W1);
    cudaGetSymbolAddress((void**)&X1,  g_X1);
    cudaGetSymbolAddress((void**)&W2,  g_W2);
    cudaGetSymbolAddress((void**)&X2,  g_X2);
    cudaGetSymbolAddress((void**)&W3,  g_W3);
    cudaGetSymbolAddress((void**)&Xr2, g_Xr2);
    cudaGetSymbolAddress((void**)&W4,  g_W4);
    cudaGetSymbolAddress((void**)&gp,  g_gp);
    cudaGetSymbolAddress((void**)&C9,  g_C9);
    cudaGetSymbolAddress((void**)&cls1T, g_cls1T);
    cudaGetSymbolAddress((void**)&c1aT,  g_c1aT);

    const int SM_C1 = (128 + 64) * 144 * 3;    // 82944
    const int SM_BB = (128 + 128) * 144 * 3;   // 110592
    const int SM_C4 = (128 + 48) * 144 * 3;    // 76032
    const int SM_FF = 53056;
    cudaFuncSetAttribute(gemm_mma<128, 64, 2, true>,   cudaFuncAttributeMaxDynamicSharedMemorySize, SM_C1);
    cudaFuncSetAttribute(gemm_mma<128, 128, 2, true>,  cudaFuncAttributeMaxDynamicSharedMemorySize, SM_BB);
    cudaFuncSetAttribute(gemm_mma<128, 128, 2, false>, cudaFuncAttributeMaxDynamicSharedMemorySize, SM_BB);
    cudaFuncSetAttribute(gemm_mma<128, 48, 1, true>,   cudaFuncAttributeMaxDynamicSharedMemorySize, SM_C4);
    cudaFuncSetAttribute(fused_final,                  cudaFuncAttributeMaxDynamicSharedMemorySize, SM_FF);

    // 1) unified prep (activations + all weights)
    prep_all<<<58944, 256>>>(res5, res2, bw, c0w, aw, c1w, Xs5, Xr2, W1, W2, W4, W3);
    // 2) conv1 GEMM: K = 18432, split-K x4 (72 chunks each, grid 512 = 2 waves)
    gemm_mma<128, 64, 2, true><<<dim3(8, 16, 4), 256, SM_C1>>>(
        Xs5, W1, 2048, 16, 16, 72, 18432, 4, 512,
        nullptr, nullptr, nullptr, cls1T, 512);
    // 3) reduce -> X1 fp16
    reduce_aug<<<(2048 * 512 / 4) / 256, 256>>>(cls1T, 4, 2048, 512, nullptr, bn1s, bn1h, X1);
    // 4) global pool
    gp_reduce<<<8, 512>>>(X1, gp);
    // 5) C9 correction table
    c9_kernel<<<dim3(64, 8), 128>>>(c0w, gp, C9);
    // 6) conv2 GEMM: K = 4608, split-K x2 (grid 256 = 1 wave)
    gemm_mma<128, 128, 2, true><<<dim3(8, 16, 2), 256, SM_BB>>>(
        X1, W2, 512, 16, 16, 36, 4608, 4, 1024,
        nullptr, nullptr, nullptr, cls1T, 1024);
    // 7) reduce (+C9) -> X2 fp16
    reduce_aug<<<(2048 * 1024 / 4) / 256, 256>>>(cls1T, 2, 2048, 1024, C9, bn2s, bn2h, X2);
    // 8) cls1 GEMM: K = 1024 (16 chunks) -> cls1T fp32
    gemm_mma<128, 128, 2, false><<<dim3(39, 16, 1), 256, SM_BB>>>(
        X2, W3, 1024, 16, 16, 16, 1024, 1, NOUT,
        nullptr, nullptr, c1b, cls1T, NOUT);
    // 9) c1a GEMM: K = 2304 (36 chunks) -> c1aT fp32
    gemm_mma<128, 48, 1, true><<<dim3(1, 1024, 1), 256, SM_C4>>>(
        Xr2, W4, 256, 128, 128, 36, 2304, 2, 48,
        bn3s, bn3h, nullptr, c1aT, 48);
    // 10) fused tail (HMMA stage-2)
    fused_final<<<dim3(256, 8), 256, SM_FF>>>(cls1T, c1aT, bw2, bb2, cats, cath, out);
}

// round 14
// speedup vs baseline: 2.7119x; 1.0139x over previous
#include <cuda_runtime.h>
#include <cuda_fp16.h>
#include <cstdint>

typedef __half h16;
#define NOUT 4928

// ---------------- scratch (device globals; sizes in elements) ----------------
__device__ __align__(16) h16 g_Xs5[(size_t)2048 * 2048];     // res5 fp16 [pos][2048]
__device__ __align__(16) h16 g_W1 [(size_t)512 * 18432];     // conv1 W fp16
__device__ __align__(16) h16 g_X1 [(size_t)2048 * 512];      // x1 fp16
__device__ __align__(16) h16 g_W2 [(size_t)1024 * 4608];     // conv2 W fp16 (moving 512 cin)
__device__ __align__(16) h16 g_X2 [(size_t)2048 * 1024];     // x2 fp16 (single)
__device__ __align__(16) h16 g_W3 [(size_t)4992 * 1024];     // cls1 W fp16 (oc padded)
__device__ __align__(16) h16 g_Xr2[(size_t)131072 * 256];    // res2 fp16
__device__ __align__(16) h16 g_W4 [(size_t)64 * 2304];       // c1a W fp16
__device__ float g_gpp[8 * 16 * 512];                        // gp partials
__device__ float g_C9 [(size_t)8 * 1024 * 9];
__device__ float g_cls1T[(size_t)2048 * NOUT];               // also split-K partial buffer
__device__ float g_c1aT [(size_t)131072 * 48];

// ---------------- helpers ----------------
__device__ __forceinline__ unsigned s2u(const void* p) {
    return (unsigned)__cvta_generic_to_shared(p);
}
__device__ __forceinline__ void cpa16(unsigned d, const void* s, unsigned sz) {
    asm volatile("cp.async.ca.shared.global [%0], [%1], 16, %2;" :: "r"(d), "l"(s), "r"(sz));
}
__device__ __forceinline__ void cpa_commit() {
    asm volatile("cp.async.commit_group;" ::: "memory");
}
template<int N> __device__ __forceinline__ void cpa_wait() {
    asm volatile("cp.async.wait_group %0;" :: "n"(N) : "memory");
}
__device__ __forceinline__ void ldm4(unsigned* r, unsigned a) {
    asm volatile("ldmatrix.sync.aligned.m8n8.x4.shared.b16 {%0,%1,%2,%3}, [%4];"
        : "=r"(r[0]), "=r"(r[1]), "=r"(r[2]), "=r"(r[3]) : "r"(a));
}
__device__ __forceinline__ void mma16816(float* d, const unsigned* a, const unsigned* b) {
    asm volatile("mma.sync.aligned.m16n8k16.row.col.f32.f16.f16.f32 "
        "{%0,%1,%2,%3}, {%4,%5,%6,%7}, {%8,%9}, {%0,%1,%2,%3};"
        : "+f"(d[0]), "+f"(d[1]), "+f"(d[2]), "+f"(d[3])
        : "r"(a[0]), "r"(a[1]), "r"(a[2]), "r"(a[3]), "r"(b[0]), "r"(b[1]));
}

// =====================================================================
// HMMA fp16 GEMM: BK=64, 3-stage cp.async pipeline, 2 CTAs/SM.
// epi: 1 = +bias -> fp32 (guarded); 2 = BN+ReLU -> fp32 (guarded);
//      4 = raw fp32 split-K partial at [blockIdx.z][M][ofc]
// =====================================================================
template<int BM, int BN, int WS, bool CONV3>
__global__ __launch_bounds__(256, 2) void gemm_mma(
    const h16* __restrict__ A, const h16* __restrict__ B,
    int C3, int imh, int imw, int nk, int Kb,
    int epi, int nvalid,
    const float* __restrict__ scale, const float* __restrict__ shift,
    const float* __restrict__ bias,
    float* __restrict__ Of, int ofc)
{
    constexpr int WM = BM / (8 / WS), WN = BN / WS;
    constexpr int MT = WM / 16;
    constexpr int NT = WN / 8;
    constexpr int NF = WN / 16;
    constexpr int AJ = BM / 32;
    constexpr int BJ = (BN * 8 + 255) / 256;
    constexpr int ABYTES = BM * 144, STG = (BM + BN) * 144;

    extern __shared__ __align__(16) char sm[];
    const int tid = threadIdx.x;
    const int nb = blockIdx.x, mtile = blockIdx.y;
    const int kzoff = blockIdx.z * nk;
    const int warp = tid >> 5, lane = tid & 31;
    const int m0 = (warp / WS) * WM, n0 = (warp % WS) * WN;
    const unsigned sbase = s2u(sm);
    const int imgpix = imh * imw;
    const int vec = tid & 7;

    int arow[AJ], ay[AJ], ax[AJ], apb[AJ];
#pragma unroll
    for (int j = 0; j < AJ; j++) {
        arow[j] = (tid >> 3) + j * 32;
        int g = mtile * BM + arow[j];
        if (CONV3) {
            int bb = g / imgpix, lp = g - bb * imgpix;
            ay[j] = lp / imw; ax[j] = lp - ay[j] * imw; apb[j] = bb * imgpix;
        } else { ay[j] = 0; ax[j] = 0; apb[j] = g; }
    }

    auto load_chunk = [&](int kc, int st) {
        unsigned Ab = sbase + st * STG;
        unsigned Bb = Ab + ABYTES;
        int k0 = (kzoff + kc) * 64;
        int dy = 0, dx = 0, cb = k0;
        if (CONV3) {
            int rk = k0 / C3; cb = k0 - rk * C3;
            int r3 = rk / 3; dy = r3 - 1; dx = rk - r3 * 3 - 1;
        }
#pragma unroll
        for (int j = 0; j < AJ; j++) {
            const h16* src;
            unsigned sz = 16;
            if (CONV3) {
                int y2 = ay[j] + dy, x2 = ax[j] + dx;
                bool v = ((unsigned)y2 < (unsigned)imh) && ((unsigned)x2 < (unsigned)imw);
                src = A + (size_t)(apb[j] + y2 * imw + x2) * C3 + cb + vec * 8;
                if (!v) { src = A; sz = 0; }
            } else {
                src = A + (size_t)apb[j] * C3 + k0 + vec * 8;
            }
            cpa16(Ab + arow[j] * 144 + vec * 16, src, sz);
        }
#pragma unroll
        for (int j = 0; j < BJ; j++) {
            int item = tid + 256 * j;
            int row = item >> 3;
            if ((BN * 8 % 256 == 0) || item < BN * 8)
                cpa16(Bb + row * 144 + (item & 7) * 16,
                      B + (size_t)(nb * BN + row) * Kb + k0 + (item & 7) * 8, 16);
        }
    };

    float acc[MT][NT][4];
#pragma unroll
    for (int a = 0; a < MT; a++)
#pragma unroll
        for (int b2 = 0; b2 < NT; b2++)
#pragma unroll
            for (int c = 0; c < 4; c++) acc[a][b2][c] = 0.f;

    auto compute = [&](int st) {
        unsigned Ab = sbase + st * STG;
        unsigned Bb = Ab + ABYTES;
#pragma unroll
        for (int step = 0; step < 4; step++) {
            unsigned af[MT][4], bfr[NF][4];
            {
                int ch = step * 2 + (lane >> 4);
#pragma unroll
                for (int i = 0; i < MT; i++)
                    ldm4(af[i], Ab + (m0 + 16 * i + (lane & 15)) * 144 + ch * 16);
            }
            {
                int rr = (lane & 7) + ((lane >> 4) << 3);
                int ch = step * 2 + ((lane >> 3) & 1);
#pragma unroll
                for (int i = 0; i < NF; i++)
                    ldm4(bfr[i], Bb + (n0 + 16 * i + rr) * 144 + ch * 16);
            }
#pragma unroll
            for (int mt = 0; mt < MT; mt++)
#pragma unroll
                for (int nt = 0; nt < NT; nt++)
                    mma16816(acc[mt][nt], af[mt], &bfr[nt >> 1][(nt & 1) * 2]);
        }
    };

    load_chunk(0, 0);
    cpa_commit();
    if (nk > 1) load_chunk(1, 1);
    cpa_commit();
    int st2 = 2;
    for (int kc = 0; kc < nk; kc++) {
        cpa_wait<1>();
        __syncthreads();
        if (kc + 2 < nk) {
            load_chunk(kc + 2, st2);
            if (++st2 == 3) st2 = 0;
        }
        cpa_commit();
        compute(kc % 3);
    }

    // ---- epilogue ----
    float* dstz = Of;
    if (epi == 4)
        dstz = Of + (size_t)blockIdx.z * ((size_t)gridDim.y * BM) * ofc;
#pragma unroll
    for (int mt = 0; mt < MT; mt++)
#pragma unroll
        for (int nt = 0; nt < NT; nt++) {
            float* d = acc[mt][nt];
            int row = mtile * BM + m0 + mt * 16 + (lane >> 2);
            int col = nb * BN + n0 + nt * 8 + (lane & 3) * 2;
#pragma unroll
            for (int h = 0; h < 2; h++) {
                int r = row + h * 8;
                float v0 = d[h * 2 + 0], v1 = d[h * 2 + 1];
                if (epi == 4) {
                    *(float2*)(dstz + (size_t)r * ofc + col) = make_float2(v0, v1);
                } else if (epi == 1) {
                    if (col < nvalid) {
                        float2 o = make_float2(v0 + bias[col], v1 + bias[col + 1]);
                        *(float2*)(Of + (size_t)r * ofc + col) = o;
                    }
                } else {
                    if (col < nvalid) {
                        float2 o;
                        o.x = fmaxf(fmaf(v0, scale[col], shift[col]), 0.f);
                        o.y = fmaxf(fmaf(v1, scale[col + 1], shift[col + 1]), 0.f);
                        *(float2*)(Of + (size_t)r * ofc + col) = o;
                    }
                }
            }
        }
}

// ---------------- reduce split-K partials + (opt C9) + BN/ReLU -> fp16 ----------------
__global__ __launch_bounds__(256) void reduce_aug(
    const float* __restrict__ P, int ns, int M, int C,
    const float* __restrict__ corr,
    const float* __restrict__ scale, const float* __restrict__ shift,
    h16* __restrict__ out)
{
    int idx = (blockIdx.x * 256 + threadIdx.x) * 4;
    int r = idx / C, col = idx - r * C;
    if (r >= M) return;
    float4 v = *(const float4*)(P + (size_t)r * C + col);
    for (int s = 1; s < ns; s++) {
        float4 p = *(const float4*)(P + ((size_t)s * M + r) * C + col);
        v.x += p.x; v.y += p.y; v.z += p.z; v.w += p.w;
    }
    if (corr) {
        int lp = r & 255, y = lp >> 4, xp = lp & 15;
        int cls = ((y == 0) ? 0 : ((y == 15) ? 6 : 3))
                + ((xp == 0) ? 0 : ((xp == 15) ? 2 : 1));
        const float* cp = corr + (size_t)(r >> 8) * 1024 * 9 + (size_t)col * 9 + cls;
        v.x += cp[0]; v.y += cp[9]; v.z += cp[18]; v.w += cp[27];
    }
    float4 sc = *(const float4*)(scale + col);
    float4 sh = *(const float4*)(shift + col);
    v.x = fmaxf(fmaf(v.x, sc.x, sh.x), 0.f);
    v.y = fmaxf(fmaf(v.y, sc.y, sh.y), 0.f);
    v.z = fmaxf(fmaf(v.z, sc.z, sh.z), 0.f);
    v.w = fmaxf(fmaf(v.w, sc.w, sh.w), 0.f);
    ushort4 u;
    u.x = __half_as_ushort(__float2half_rn(v.x));
    u.y = __half_as_ushort(__float2half_rn(v.y));
    u.z = __half_as_ushort(__float2half_rn(v.z));
    u.w = __half_as_ushort(__float2half_rn(v.w));
    *(ushort4*)(out + (size_t)r * C + col) = u;
}

// =====================================================================
// Unified prep. Activation tiles are 64ch x 32pos so BOTH fp32 reads and
// fp16 writes are 128B per transaction. Segments by blockIdx.x:
//   [0, 2048)        res5  (8 pgrp x 32 cgrp x 8 b)
//   [2048, 18432)    res2  (512 pgrp x 4 cgrp x 8 b)
//   [18432, 18944)   conv1 W transpose (coalesced via smem)
//   [18944, 19968)   conv2 W transpose
//   [19968, 40512)   c1a W + cls1 W elementwise
// =====================================================================
__global__ __launch_bounds__(256) void prep_all(
    const float* __restrict__ res5, const float* __restrict__ res2,
    const float* __restrict__ bw,   const float* __restrict__ c0w,
    const float* __restrict__ aw,   const float* __restrict__ c1w,
    h16* __restrict__ Xs5, h16* __restrict__ Xr2,
    h16* __restrict__ W1,  h16* __restrict__ W2,
    h16* __restrict__ W4,  h16* __restrict__ W3)
{
    __shared__ float tt[64][33];
    __shared__ float tw[9][132];
    const int blk = blockIdx.x, tid = threadIdx.x;

    if (blk < 18432) {
        // activation transpose: 64 channels x 32 positions per tile
        const float* in; h16* out; int C, HW, b, c0, p0;
        if (blk < 2048) {
            in = res5; out = Xs5; C = 2048; HW = 256;
            p0 = (blk & 7) * 32; c0 = ((blk >> 3) & 31) * 64; b = blk >> 8;
        } else {
            int l = blk - 2048;
            in = res2; out = Xr2; C = 256; HW = 16384;
            p0 = (l & 511) * 32; c0 = ((l >> 9) & 3) * 64; b = l >> 11;
        }
        {
            const int tx = tid & 31, ty = tid >> 5;     // ty in 0..7
#pragma unroll
            for (int r = 0; r < 8; r++)
                tt[ty + 8 * r][tx] = in[((size_t)b * C + c0 + ty + 8 * r) * HW + p0 + tx];
        }
        __syncthreads();
        {
            const int cc = tid & 63, pq = tid >> 6;     // pq in 0..3
#pragma unroll
            for (int r = 0; r < 8; r++) {
                int p = pq + 4 * r;                      // 32 positions
                out[((size_t)b * HW + p0 + p) * C + c0 + cc] =
                    __float2half_rn(tt[cc][p]);
            }
        }
    } else if (blk < 19968) {
        // conv weight transpose, staged through smem for coalesced reads
        const float* wsrc; h16* wdst; int C, CI, ntile, oc;
        if (blk < 18944) { oc = blk - 18432; wsrc = bw;  wdst = W1; C = 2048; CI = 2048; ntile = 16; }
        else             { oc = blk - 18944; wsrc = c0w; wdst = W2; C = 512;  CI = 1024; ntile = 4; }
        for (int ct = 0; ct < ntile; ct++) {
            int c0 = ct * 128;
            for (int i = tid; i < 1152; i += 256) {
                int c = i / 9, tap = i - c * 9;
                tw[tap][c] = wsrc[(size_t)oc * CI * 9 + (size_t)(c0 + c) * 9 + tap];
            }
            __syncthreads();
            for (int i = tid; i < 1152; i += 256) {
                int tap = i >> 7, c = i & 127;
                wdst[(size_t)oc * 9 * C + (size_t)tap * C + c0 + c] =
                    __float2half_rn(tw[tap][c]);
            }
            __syncthreads();
        }
    } else {
        // small weights, elementwise
        const int N4 = 64 * 9 * 256;
        int idx = (blk - 19968) * 256 + tid;
        if (idx < N4) {
            int oc = idx / (9 * 256); int rem = idx - oc * 9 * 256;
            int tap = rem / 256; int c = rem - tap * 256;
            float v = (oc < 48) ? aw[((size_t)oc * 256 + c) * 9 + tap] : 0.f;
            W4[(size_t)oc * 2304 + (size_t)tap * 256 + c] = __float2half_rn(v);
        } else {
            int i2 = idx - N4;
            if (i2 < 4992 * 1024) {
                int oc = i2 >> 10;
                float v = (oc < NOUT) ? c1w[i2] : 0.f;
                W3[i2] = __float2half_rn(v);
            }
        }
    }
}

// ---------------- gp partials: grid (8 b, 16 pos-groups), 512 thr ----------------
__global__ __launch_bounds__(512) void gp_part(
    const h16* __restrict__ X1, float* __restrict__ gpp)
{
    const int b = blockIdx.x, pg = blockIdx.y, c = threadIdx.x;
    float s = 0.f;
#pragma unroll
    for (int i = 0; i < 16; i++) {
        int p = pg * 16 + i;
        s += __half2float(X1[((size_t)(b * 256 + p)) * 512 + c]);
    }
    gpp[((size_t)(b * 16 + pg)) * 512 + c] = s;
}

// ---------------- C9: fold gp partials + per-(b, oc, class) correction ----------------
__global__ __launch_bounds__(128) void c9_kernel(
    const float* __restrict__ w, const float* __restrict__ gpp, float* __restrict__ C9)
{
    __shared__ float sgp[512];
    __shared__ float sT[16][9];
    const int b = blockIdx.y, oc0 = blockIdx.x * 16, tid = threadIdx.x;
    for (int i = tid; i < 512; i += 128) {
        float s = 0.f;
#pragma unroll
        for (int pg = 0; pg < 16; pg++)
            s += gpp[((size_t)(b * 16 + pg)) * 512 + i];
        sgp[i] = s * (1.f / 256.f);
    }
    __syncthreads();

    const int oc = oc0 + (tid >> 3), ln = tid & 7;
    float t[9];
#pragma unroll
    for (int k = 0; k < 9; k++) t[k] = 0.f;
    for (int c = ln * 64; c < ln * 64 + 64; c++) {
        float g = sgp[c];
        const float* wp = w + ((size_t)oc * 1024 + 512 + c) * 9;
#pragma unroll
        for (int k = 0; k < 9; k++) t[k] = fmaf(wp[k], g, t[k]);
    }
#pragma unroll
    for (int o = 4; o; o >>= 1)
#pragma unroll
        for (int k = 0; k < 9; k++) t[k] += __shfl_down_sync(0xffffffffu, t[k], o, 8);
    if (ln == 0)
#pragma unroll
        for (int k = 0; k < 9; k++) sT[tid >> 3][k] = t[k];
    __syncthreads();

    for (int i = tid; i < 144; i += 128) {
        int o = i / 9, cls = i - (i / 9) * 9;
        int fy = cls / 3, fx = cls - fy * 3;
        float s = 0.f;
#pragma unroll
        for (int ky = 0; ky < 3; ky++) {
            if ((fy == 0 && ky == 0) || (fy == 2 && ky == 2)) continue;
#pragma unroll
            for (int kx = 0; kx < 3; kx++) {
                if ((fx == 0 && kx == 0) || (fx == 2 && kx == 2)) continue;
                s += sT[o][ky * 3 + kx];
            }
        }
        C9[((size_t)b * 1024 + oc0 + o) * 9 + cls] = s;
    }
}

// =====================================================================
// fused: c1b + coord + cat-BN + MLP stages 0/1 (scalar) + stage 2 on HMMA.
// =====================================================================
__global__ __launch_bounds__(256) void fused_final(
    const float* __restrict__ cls1T, const float* __restrict__ c1aT,
    const float* __restrict__ c1b_w, const float* __restrict__ c1b_b,
    const float* __restrict__ cat_scale, const float* __restrict__ cat_shift,
    float* __restrict__ out)
{
    extern __shared__ __align__(16) char fsm[];
    float* sP  = (float*)fsm;                    // 4928 floats
    float* sWb = (float*)(fsm + 19712);          // 784 floats
    char*  U   = fsm + 19712 + 3136;
    float* sAc = (float*)U;                      // 48*64
    float* sI  = (float*)(U + 12288);            // 18*64
    float* sH0 = (float*)(U + 16896);            // 16*64
    float* sH1 = (float*)(U + 20992);            // 16*64
    char*  sAw = U;                              // late: 256 x 80B
    char*  sB  = U + 25088;                      // late: 64 x 80B

    const int b = blockIdx.y, lpos = blockIdx.x;
    const int ly = lpos >> 4, lx = lpos & 15;
    const int tid = threadIdx.x;
    const int px = tid & 63, q = tid >> 6;
    const int py = px >> 3, pxx = px & 7;
    const int lane = tid & 31;

    const float* pp = cls1T + (size_t)(b * 256 + lpos) * NOUT;
    for (int i = tid; i < NOUT; i += 256) sP[i] = pp[i];
    for (int i = tid; i < 48 * 64; i += 256) {
        int p = i / 48, ch = i - p * 48;
        int yy = ly * 8 + (p >> 3), xx = lx * 8 + (p & 7);
        sAc[ch * 64 + p] = c1aT[((size_t)b * 16384 + yy * 128 + xx) * 48 + ch];
    }
    for (int i = tid; i < 768; i += 256) sWb[i] = c1b_w[i];
    if (tid < 16) sWb[768 + tid] = c1b_b[tid];
    __syncthreads();

#pragma unroll
    for (int jj = 0; jj < 4; jj++) {
        int j = q * 4 + jj;
        float s = sWb[768 + j];
#pragma unroll
        for (int c = 0; c < 48; c++)
            s = fmaf(sAc[c * 64 + px], sWb[j * 48 + c], s);
        sI[(2 + j) * 64 + px] = fmaf(s, cat_scale[2 + j], cat_shift[2 + j]);
    }
    if (q == 0) {
        sI[px]      = fmaf((float)pxx * 0.125f, cat_scale[0], cat_shift[0]);
        sI[64 + px] = fmaf((float)py  * 0.125f, cat_scale[1], cat_shift[1]);
    }
    __syncthreads();

#pragma unroll
    for (int jj = 0; jj < 4; jj++) {
        int o = q * 4 + jj;
        float s = sP[288 + o];
#pragma unroll
        for (int c = 0; c < 18; c++)
            s = fmaf(sP[o * 18 + c], sI[c * 64 + px], s);
        sH0[o * 64 + px] = fmaxf(s, 0.f);
    }
    __syncthreads();

#pragma unroll
    for (int jj = 0; jj < 4; jj++) {
        int o = q * 4 + jj;
        float s = sP[560 + o];
#pragma unroll
        for (int c = 0; c < 16; c++)
            s = fmaf(sP[304 + o * 16 + c], sH0[c * 64 + px], s);
        sH1[o * 64 + px] = fmaxf(s, 0.f);
    }
    __syncthreads();

    for (int t = tid; t < 1024; t += 256) {
        int p2 = t & 63, c = t >> 6;
        h16 hh = __float2half_rn(sH1[c * 64 + p2]);
        *(h16*)(sB + p2 * 80 + c * 2) = hh;
        *(h16*)(sB + p2 * 80 + 32 + c * 2) = hh;
    }
    for (int t = tid; t < 4096; t += 256) {
        int o = t >> 4, c = t & 15;
        float w = sP[576 + t];
        h16 wh = __float2half_rn(w);
        h16 wl = __float2half_rn(w - __half2float(wh));
        *(h16*)(sAw + o * 80 + c * 2) = wh;
        *(h16*)(sAw + o * 80 + 32 + c * 2) = wl;
    }
    __syncthreads();

    const int warp = tid >> 5;
    const int m0 = warp * 32;
    const unsigned sAb = s2u(sAw), sBb = s2u(sB);
    float acc[2][8][4];
#pragma unroll
    for (int a = 0; a < 2; a++)
#pragma unroll
        for (int n2 = 0; n2 < 8; n2++)
#pragma unroll
            for (int c = 0; c < 4; c++) acc[a][n2][c] = 0.f;

#pragma unroll
    for (int step = 0; step < 2; step++) {
        unsigned af[2][4], bfr[4][4];
        int ch = step * 2 + (lane >> 4);
#pragma unroll
        for (int i = 0; i < 2; i++)
            ldm4(af[i], sAb + (m0 + 16 * i + (lane & 15)) * 80 + ch * 16);
        int rr = (lane & 7) + ((lane >> 4) << 3);
        int chB = step * 2 + ((lane >> 3) & 1);
#pragma unroll
        for (int i = 0; i < 4; i++)
            ldm4(bfr[i], sBb + (16 * i + rr) * 80 + chB * 16);
#pragma unroll
        for (int mt = 0; mt < 2; mt++)
#pragma unroll
            for (int nt = 0; nt < 8; nt++)
                mma16816(acc[mt][nt], af[mt], &bfr[nt >> 1][(nt & 1) * 2]);
    }

    float* obase = out + ((size_t)b << 22) + (ly * 8) * 128 + lx * 8;
#pragma unroll
    for (int mt = 0; mt < 2; mt++)
#pragma unroll
        for (int nt = 0; nt < 8; nt++) {
            float* d = acc[mt][nt];
            int o = m0 + mt * 16 + (lane >> 2);
            int pxx2 = (lane & 3) * 2;
#pragma unroll
            for (int h2 = 0; h2 < 2; h2++) {
                int oo = o + h2 * 8;
                float bv = sP[4672 + oo];
                float2 v = make_float2(d[h2 * 2] + bv, d[h2 * 2 + 1] + bv);
                *(float2*)(obase + ((size_t)oo << 14) + nt * 128 + pxx2) = v;
            }
        }
}

// ---------------- host launcher ----------------
extern "C" void kernel_launch(void* const* d_in, const int* in_sizes, int n_in,
                              void* d_out, int out_size)
{
    const float* res5 = (const float*)d_in[0];
    const float* res2 = (const float*)d_in[1];
    const float* bw   = (const float*)d_in[2];
    const float* bn1s = (const float*)d_in[3];
    const float* bn1h = (const float*)d_in[4];
    const float* c0w  = (const float*)d_in[5];
    const float* bn2s = (const float*)d_in[6];
    const float* bn2h = (const float*)d_in[7];
    const float* c1w  = (const float*)d_in[8];
    const float* c1b  = (const float*)d_in[9];
    const float* aw   = (const float*)d_in[10];
    const float* bn3s = (const float*)d_in[11];
    const float* bn3h = (const float*)d_in[12];
    const float* bw2  = (const float*)d_in[13];
    const float* bb2  = (const float*)d_in[14];
    const float* cats = (const float*)d_in[15];
    const float* cath = (const float*)d_in[16];
    float* out = (float*)d_out;

    h16 *Xs5, *W1, *X1, *W2, *X2, *W3, *Xr2, *W4;
    float *gpp, *C9, *cls1T, *c1aT;
    cudaGetSymbolAddress((void**)&Xs5, g_Xs5);
    cudaGetSymbolAddress((void**)&W1,  g_W1);
    cudaGetSymbolAddress((void**)&X1,  g_X1);
    cudaGetSymbolAddress((void**)&W2,  g_W2);
    cudaGetSymbolAddress((void**)&X2,  g_X2);
    cudaGetSymbolAddress((void**)&W3,  g_W3);
    cudaGetSymbolAddress((void**)&Xr2, g_Xr2);
    cudaGetSymbolAddress((void**)&W4,  g_W4);
    cudaGetSymbolAddress((void**)&gpp, g_gpp);
    cudaGetSymbolAddress((void**)&C9,  g_C9);
    cudaGetSymbolAddress((void**)&cls1T, g_cls1T);
    cudaGetSymbolAddress((void**)&c1aT,  g_c1aT);

    const int SM_C1 = (128 + 64) * 144 * 3;    // 82944
    const int SM_BB = (128 + 128) * 144 * 3;   // 110592
    const int SM_C4 = (128 + 48) * 144 * 3;    // 76032
    const int SM_FF = 53056;
    cudaFuncSetAttribute(gemm_mma<128, 64, 2, true>,   cudaFuncAttributeMaxDynamicSharedMemorySize, SM_C1);
    cudaFuncSetAttribute(gemm_mma<128, 128, 2, true>,  cudaFuncAttributeMaxDynamicSharedMemorySize, SM_BB);
    cudaFuncSetAttribute(gemm_mma<128, 128, 2, false>, cudaFuncAttributeMaxDynamicSharedMemorySize, SM_BB);
    cudaFuncSetAttribute(gemm_mma<128, 48, 1, true>,   cudaFuncAttributeMaxDynamicSharedMemorySize, SM_C4);
    cudaFuncSetAttribute(fused_final,                  cudaFuncAttributeMaxDynamicSharedMemorySize, SM_FF);

    // 1) unified prep (activations + all weights)
    prep_all<<<40512, 256>>>(res5, res2, bw, c0w, aw, c1w, Xs5, Xr2, W1, W2, W4, W3);
    // 2) conv1 GEMM: K = 18432, split-K x4 -> partials
    gemm_mma<128, 64, 2, true><<<dim3(8, 16, 4), 256, SM_C1>>>(
        Xs5, W1, 2048, 16, 16, 72, 18432, 4, 512,
        nullptr, nullptr, nullptr, cls1T, 512);
    // 3) reduce -> X1 fp16
    reduce_aug<<<(2048 * 512 / 4) / 256, 256>>>(cls1T, 4, 2048, 512, nullptr, bn1s, bn1h, X1);
    // 4) conv2 GEMM (profiled slot): K = 4608, split-K x2 -> partials into c1aT
    //    (c1aT is unused at this point and big enough: 2 * 2048 * 1024 floats)
    gemm_mma<128, 128, 2, true><<<dim3(8, 16, 2), 256, SM_BB>>>(
        X1, W2, 512, 16, 16, 36, 4608, 4, 1024,
        nullptr, nullptr, nullptr, c1aT, 1024);
    // 5) gp partials
    gp_part<<<dim3(8, 16), 512>>>(X1, gpp);
    // 6) C9 correction table (folds gp partials)
    c9_kernel<<<dim3(64, 8), 128>>>(c0w, gpp, C9);
    // 7) reduce (+C9) -> X2 fp16
    reduce_aug<<<(2048 * 1024 / 4) / 256, 256>>>(c1aT, 2, 2048, 1024, C9, bn2s, bn2h, X2);
    // 8) cls1 GEMM: K = 1024 (16 chunks) -> cls1T fp32
    gemm_mma<128, 128, 2, false><<<dim3(39, 16, 1), 256, SM_BB>>>(
        X2, W3, 1024, 16, 16, 16, 1024, 1, NOUT,
        nullptr, nullptr, c1b, cls1T, NOUT);
    // 9) c1a GEMM: K = 2304 (36 chunks) -> c1aT fp32
    gemm_mma<128, 48, 1, true><<<dim3(1, 1024, 1), 256, SM_C4>>>(
        Xr2, W4, 256, 128, 128, 36, 2304, 2, 48,
        bn3s, bn3h, nullptr, c1aT, 48);
    // 10) fused tail (HMMA stage-2)
    fused_final<<<dim3(256, 8), 256, SM_FF>>>(cls1T, c1aT, bw2, bb2, cats, cath, out);
}